// round 2
// baseline (speedup 1.0000x reference)
#include <cuda_runtime.h>
#include <mma.h>
using namespace nvcuda;

#define NN 50000
#define EE 850000
#define HDIM 128

// ---------------- scratch (device globals) ----------------------------------
__device__ float g_h0[NN * HDIM];
__device__ float g_h1[NN * HDIM];
__device__ float g_feat[NN * HDIM];
__device__ float g_el[NN * 4];
__device__ float g_er[NN * 4];
__device__ float g_wlr[HDIM * 8];
__device__ int   g_deg[NN];
__device__ int   g_rowptr[NN + 1];
__device__ int   g_cursor[NN];
__device__ int   g_csr[EE];
__device__ int   g_partial[256];
__device__ int   g_poff[256];
__device__ float g_bnstat[256];   // [0:128) sums, [128:256) sumsq

__device__ __forceinline__ float eluf(float x) { return x > 0.f ? x : (__expf(x) - 1.f); }
__device__ __forceinline__ float lrelu(float x) { return x > 0.f ? x : 0.2f * x; }

// ---------------- CSR build --------------------------------------------------
__global__ void k_hist(const int* __restrict__ dst, int* deg) {
    int i = blockIdx.x * blockDim.x + threadIdx.x;
    if (i < EE) atomicAdd(&deg[dst[i]], 1);
}

__device__ __forceinline__ int block_scan_excl(int v, int t) {
    __shared__ int ws[8];
    int lane = t & 31, w = t >> 5;
    int incl = v;
#pragma unroll
    for (int o = 1; o < 32; o <<= 1) {
        int u = __shfl_up_sync(0xffffffffu, incl, o);
        if (lane >= o) incl += u;
    }
    if (lane == 31) ws[w] = incl;
    __syncthreads();
    if (t == 0) {
        int run = 0;
#pragma unroll
        for (int i = 0; i < 8; i++) { int x = ws[i]; ws[i] = run; run += x; }
    }
    __syncthreads();
    return incl - v + ws[w];
}

__global__ void k_scan1(const int* __restrict__ deg, int* __restrict__ partial) {
    __shared__ int ws[8];
    int t = threadIdx.x, idx = blockIdx.x * 256 + t;
    int v = (idx < NN) ? deg[idx] : 0;
#pragma unroll
    for (int o = 16; o > 0; o >>= 1) v += __shfl_xor_sync(0xffffffffu, v, o);
    if ((t & 31) == 0) ws[t >> 5] = v;
    __syncthreads();
    if (t == 0) {
        int s = 0;
#pragma unroll
        for (int i = 0; i < 8; i++) s += ws[i];
        partial[blockIdx.x] = s;
    }
}

__global__ void k_scan2(const int* __restrict__ partial, int* __restrict__ poff, int nblk) {
    int t = threadIdx.x;
    int v = (t < nblk) ? partial[t] : 0;
    int excl = block_scan_excl(v, t);
    if (t < nblk) poff[t] = excl;
}

__global__ void k_scan3(const int* __restrict__ deg, const int* __restrict__ poff,
                        int* __restrict__ rowptr, int* __restrict__ cursor) {
    int t = threadIdx.x, idx = blockIdx.x * 256 + t;
    int v = (idx < NN) ? deg[idx] : 0;
    int excl = block_scan_excl(v, t);
    int res = poff[blockIdx.x] + excl;
    if (idx <= NN) rowptr[idx] = res;
    if (idx < NN) cursor[idx] = res;
}

__global__ void k_fill(const int* __restrict__ src, const int* __restrict__ dst,
                       int* cursor, int* __restrict__ csr) {
    int i = blockIdx.x * blockDim.x + threadIdx.x;
    if (i < EE) {
        int d = dst[i];
        int pos = atomicAdd(&cursor[d], 1);
        csr[pos] = src[i];
    }
}

// ---------------- Wlr: fold attention vectors into GEMM ---------------------
// Wlr[k][c] : c<4 -> sum_d W[k][c*32+d]*al[c][d] ; c>=4 -> ar[c-4]
__global__ void k_wlr(const float* __restrict__ W, const float* __restrict__ al,
                      const float* __restrict__ ar, float* __restrict__ wlr) {
    int t = threadIdx.x;           // 1024 threads
    int k = t >> 3, c = t & 7;
    int h = c & 3;
    const float* a = (c < 4) ? al : ar;
    float s = 0.f;
#pragma unroll
    for (int d = 0; d < 32; d++) s += W[k * 128 + h * 32 + d] * a[h * 32 + d];
    wlr[k * 8 + c] = s;
}

// ---------------- fused TF32 GEMM + el/er ------------------------------------
// C[N,144] = A[N,128] @ [W | Wlr | 0]; cols 0-127 -> feat, 128-135 -> el/er.
__global__ void k_gemm_eler(const float* __restrict__ A, const int* __restrict__ xidx,
                            const float* __restrict__ embed,
                            const float* __restrict__ W, const float* __restrict__ Wlr,
                            float* __restrict__ feat, float4* __restrict__ el4,
                            float4* __restrict__ er4) {
    extern __shared__ float sm[];
    float* sA = sm;                    // 128 x 40
    float* sW = sm + 128 * 40;         // 32 x 152 (144 used)
    float* sE = sW + 32 * 152;         // 8 x 16 x 16
    int tid = threadIdx.x, warp = tid >> 5, lane = tid & 31;
    int row0 = blockIdx.x * 128;

    wmma::fragment<wmma::accumulator, 16, 16, 8, float> fc[9];
#pragma unroll
    for (int i = 0; i < 9; i++) wmma::fill_fragment(fc[i], 0.f);

    for (int kb = 0; kb < 4; kb++) {
        for (int i = tid; i < 4096; i += 256) {
            int r = i >> 5, c = i & 31;
            int gr = row0 + r;
            float v = 0.f;
            if (gr < NN) {
                if (xidx) v = embed[(size_t)xidx[gr] * 128 + kb * 32 + c];
                else      v = A[(size_t)gr * 128 + kb * 32 + c];
            }
            sA[r * 40 + c] = wmma::__float_to_tf32(v);
        }
        for (int i = tid; i < 32 * 144; i += 256) {
            int r = i / 144, c = i - r * 144;
            float v;
            if (c < 128)      v = W[(kb * 32 + r) * 128 + c];
            else if (c < 136) v = Wlr[(kb * 32 + r) * 8 + (c - 128)];
            else              v = 0.f;
            sW[r * 152 + c] = wmma::__float_to_tf32(v);
        }
        __syncthreads();
#pragma unroll
        for (int ks = 0; ks < 4; ks++) {
            wmma::fragment<wmma::matrix_a, 16, 16, 8, wmma::precision::tf32, wmma::row_major> fa;
            wmma::load_matrix_sync(fa, sA + (warp * 16) * 40 + ks * 8, 40);
#pragma unroll
            for (int ct = 0; ct < 9; ct++) {
                wmma::fragment<wmma::matrix_b, 16, 16, 8, wmma::precision::tf32, wmma::row_major> fb;
                wmma::load_matrix_sync(fb, sW + (ks * 8) * 152 + ct * 16, 152);
                wmma::mma_sync(fc[ct], fa, fb, fc[ct]);
            }
        }
        __syncthreads();
    }
    int wrow = row0 + warp * 16;
    if (wrow < NN) {  // NN % 16 == 0 -> whole tile valid
#pragma unroll
        for (int ct = 0; ct < 8; ct++)
            wmma::store_matrix_sync(feat + (size_t)wrow * 128 + ct * 16, fc[ct], 128,
                                    wmma::mem_row_major);
    }
    wmma::store_matrix_sync(sE + warp * 256, fc[8], 16, wmma::mem_row_major);
    __syncwarp();
    if (lane < 16 && wrow < NN) {
        float* p = sE + warp * 256 + lane * 16;
        el4[wrow + lane] = make_float4(p[0], p[1], p[2], p[3]);
        er4[wrow + lane] = make_float4(p[4], p[5], p[6], p[7]);
    }
}

// ---------------- fused per-dst softmax + aggregation + BN partial stats ----
template <bool RES, bool ACT>
__global__ void k_agg(const float4* __restrict__ feat4, const float4* __restrict__ hin4,
                      const float4* __restrict__ el4, const float4* __restrict__ er4,
                      const float* __restrict__ snorm, const int* __restrict__ rowptr,
                      const int* __restrict__ csr, float4* __restrict__ out4,
                      float* __restrict__ bnstat) {
    __shared__ float bs[1024];
    __shared__ float bq[1024];
    int warp = threadIdx.x >> 5;
    int lane = threadIdx.x & 31;
    int node = blockIdx.x * 8 + warp;   // NN divisible by 8
    int start = rowptr[node], end = rowptr[node + 1];
    int deg = end - start;
    float4 er = er4[node];
    int hl = lane >> 3;

    float4 acc;
    if (RES) acc = hin4[(size_t)node * 32 + lane];
    else acc = make_float4(0.f, 0.f, 0.f, 0.f);

    if (deg <= 32) {
        bool act = lane < deg;
        int s = act ? csr[start + lane] : 0;
        float4 v = make_float4(-3e38f, -3e38f, -3e38f, -3e38f);
        if (act) {
            float4 e = el4[s];
            v.x = lrelu(e.x + er.x); v.y = lrelu(e.y + er.y);
            v.z = lrelu(e.z + er.z); v.w = lrelu(e.w + er.w);
        }
        float4 mx = v;
#pragma unroll
        for (int o = 16; o > 0; o >>= 1) {
            mx.x = fmaxf(mx.x, __shfl_xor_sync(0xffffffffu, mx.x, o));
            mx.y = fmaxf(mx.y, __shfl_xor_sync(0xffffffffu, mx.y, o));
            mx.z = fmaxf(mx.z, __shfl_xor_sync(0xffffffffu, mx.z, o));
            mx.w = fmaxf(mx.w, __shfl_xor_sync(0xffffffffu, mx.w, o));
        }
        float4 ex = make_float4(0.f, 0.f, 0.f, 0.f);
        if (act) {
            ex.x = __expf(v.x - mx.x); ex.y = __expf(v.y - mx.y);
            ex.z = __expf(v.z - mx.z); ex.w = __expf(v.w - mx.w);
        }
        float4 sum = ex;
#pragma unroll
        for (int o = 16; o > 0; o >>= 1) {
            sum.x += __shfl_xor_sync(0xffffffffu, sum.x, o);
            sum.y += __shfl_xor_sync(0xffffffffu, sum.y, o);
            sum.z += __shfl_xor_sync(0xffffffffu, sum.z, o);
            sum.w += __shfl_xor_sync(0xffffffffu, sum.w, o);
        }
        float4 aexp;
        aexp.x = ex.x / sum.x; aexp.y = ex.y / sum.y;
        aexp.z = ex.z / sum.z; aexp.w = ex.w / sum.w;
        for (int j = 0; j < deg; j++) {
            int sj = __shfl_sync(0xffffffffu, s, j);
            float ax = __shfl_sync(0xffffffffu, aexp.x, j);
            float ay = __shfl_sync(0xffffffffu, aexp.y, j);
            float az = __shfl_sync(0xffffffffu, aexp.z, j);
            float aw = __shfl_sync(0xffffffffu, aexp.w, j);
            float a = hl < 2 ? (hl == 0 ? ax : ay) : (hl == 2 ? az : aw);
            float4 f = feat4[(size_t)sj * 32 + lane];
            acc.x += f.x * a; acc.y += f.y * a; acc.z += f.z * a; acc.w += f.w * a;
        }
    } else {
        float mx0 = -3e38f, mx1 = -3e38f, mx2 = -3e38f, mx3 = -3e38f;
        for (int k = start + lane; k < end; k += 32) {
            int s = csr[k];
            float4 e = el4[s];
            mx0 = fmaxf(mx0, lrelu(e.x + er.x)); mx1 = fmaxf(mx1, lrelu(e.y + er.y));
            mx2 = fmaxf(mx2, lrelu(e.z + er.z)); mx3 = fmaxf(mx3, lrelu(e.w + er.w));
        }
#pragma unroll
        for (int o = 16; o > 0; o >>= 1) {
            mx0 = fmaxf(mx0, __shfl_xor_sync(0xffffffffu, mx0, o));
            mx1 = fmaxf(mx1, __shfl_xor_sync(0xffffffffu, mx1, o));
            mx2 = fmaxf(mx2, __shfl_xor_sync(0xffffffffu, mx2, o));
            mx3 = fmaxf(mx3, __shfl_xor_sync(0xffffffffu, mx3, o));
        }
        float s0 = 0.f, s1 = 0.f, s2 = 0.f, s3 = 0.f;
        for (int k = start + lane; k < end; k += 32) {
            int s = csr[k];
            float4 e = el4[s];
            s0 += __expf(lrelu(e.x + er.x) - mx0);
            s1 += __expf(lrelu(e.y + er.y) - mx1);
            s2 += __expf(lrelu(e.z + er.z) - mx2);
            s3 += __expf(lrelu(e.w + er.w) - mx3);
        }
#pragma unroll
        for (int o = 16; o > 0; o >>= 1) {
            s0 += __shfl_xor_sync(0xffffffffu, s0, o);
            s1 += __shfl_xor_sync(0xffffffffu, s1, o);
            s2 += __shfl_xor_sync(0xffffffffu, s2, o);
            s3 += __shfl_xor_sync(0xffffffffu, s3, o);
        }
        float mxh = hl == 0 ? mx0 : hl == 1 ? mx1 : hl == 2 ? mx2 : mx3;
        float invh = 1.f / (hl == 0 ? s0 : hl == 1 ? s1 : hl == 2 ? s2 : s3);
        float erh = hl == 0 ? er.x : hl == 1 ? er.y : hl == 2 ? er.z : er.w;
        for (int k = start; k < end; k++) {
            int s = csr[k];
            float4 e = el4[s];
            float ev = hl == 0 ? e.x : hl == 1 ? e.y : hl == 2 ? e.z : e.w;
            float a = __expf(lrelu(ev + erh) - mxh) * invh;
            float4 f = feat4[(size_t)s * 32 + lane];
            acc.x += f.x * a; acc.y += f.y * a; acc.z += f.z * a; acc.w += f.w * a;
        }
    }
    if (ACT) {
        acc.x = eluf(acc.x); acc.y = eluf(acc.y);
        acc.z = eluf(acc.z); acc.w = eluf(acc.w);
    }
    float sn = snorm[node];
    acc.x *= sn; acc.y *= sn; acc.z *= sn; acc.w *= sn;
    out4[(size_t)node * 32 + lane] = acc;

    // BN partial stats: per-block accumulate 128-channel sums
    ((float4*)bs)[warp * 32 + lane] = acc;
    ((float4*)bq)[warp * 32 + lane] =
        make_float4(acc.x * acc.x, acc.y * acc.y, acc.z * acc.z, acc.w * acc.w);
    __syncthreads();
    int t = threadIdx.x;
    if (t < 128) {
        float s = 0.f, q = 0.f;
#pragma unroll
        for (int w = 0; w < 8; w++) { s += bs[w * 128 + t]; q += bq[w * 128 + t]; }
        atomicAdd(&bnstat[t], s);
        atomicAdd(&bnstat[128 + t], q);
    }
}

// ---------------- BN apply + elu ---------------------------------------------
__global__ void k_bnapply(float* __restrict__ h, const float* __restrict__ gamma,
                          const float* __restrict__ beta, const float* __restrict__ bnstat) {
    int i = blockIdx.x * blockDim.x + threadIdx.x;
    if (i < NN * HDIM) {
        int ch = i & 127;
        float mu = bnstat[ch] * (1.f / NN);
        float var = bnstat[128 + ch] * (1.f / NN) - mu * mu;
        float v = (h[i] - mu) * rsqrtf(var + 1e-5f) * gamma[ch] + beta[ch];
        h[i] = eluf(v);
    }
}

// ---------------- fused 2-layer classifier (tf32 first GEMM) -----------------
__global__ void k_cls(const float* __restrict__ H, const float* __restrict__ w1,
                      const float* __restrict__ b1, const float* __restrict__ w2,
                      const float* __restrict__ b2, float* __restrict__ out) {
    extern __shared__ float sm[];
    float* sA = sm;               // 128 x 36
    float* sW = sm + 128 * 36;    // 32 x 68
    float* sC = sW + 32 * 68;     // 128 x 68
    int tid = threadIdx.x, warp = tid >> 5;
    int row0 = blockIdx.x * 128;

    wmma::fragment<wmma::accumulator, 16, 16, 8, float> fc[4];
#pragma unroll
    for (int i = 0; i < 4; i++) wmma::fill_fragment(fc[i], 0.f);

    for (int kb = 0; kb < 4; kb++) {
        for (int i = tid; i < 4096; i += 256) {
            int r = i >> 5, c = i & 31;
            int gr = row0 + r;
            float v = (gr < NN) ? H[(size_t)gr * 128 + kb * 32 + c] : 0.f;
            sA[r * 36 + c] = wmma::__float_to_tf32(v);
        }
        for (int i = tid; i < 2048; i += 256) {
            int r = i >> 6, c = i & 63;
            sW[r * 68 + c] = wmma::__float_to_tf32(w1[(kb * 32 + r) * 64 + c]);
        }
        __syncthreads();
#pragma unroll
        for (int ks = 0; ks < 4; ks++) {
            wmma::fragment<wmma::matrix_a, 16, 16, 8, wmma::precision::tf32, wmma::row_major> fa;
            wmma::load_matrix_sync(fa, sA + (warp * 16) * 36 + ks * 8, 36);
#pragma unroll
            for (int ct = 0; ct < 4; ct++) {
                wmma::fragment<wmma::matrix_b, 16, 16, 8, wmma::precision::tf32, wmma::row_major> fb;
                wmma::load_matrix_sync(fb, sW + (ks * 8) * 68 + ct * 16, 68);
                wmma::mma_sync(fc[ct], fa, fb, fc[ct]);
            }
        }
        __syncthreads();
    }
#pragma unroll
    for (int ct = 0; ct < 4; ct++)
        wmma::store_matrix_sync(sC + (warp * 16) * 68 + ct * 16, fc[ct], 68, wmma::mem_row_major);
    __syncthreads();
    int row = tid >> 1, o = tid & 1;
    int gr = row0 + row;
    if (gr < NN) {
        float s = b2[o];
        for (int k = 0; k < 64; k++) {
            float hv = sC[row * 68 + k] + b1[k];
            hv = hv > 0.f ? hv : 0.f;
            s += hv * w2[k * 2 + o];
        }
        out[(size_t)gr * 2 + o] = s;
    }
}

// ---------------- host orchestration ----------------------------------------
extern "C" void kernel_launch(void* const* d_in, const int* in_sizes, int n_in,
                              void* d_out, int out_size) {
    const int* x = (const int*)d_in[0];
    const int* src = (const int*)d_in[1];
    const int* dst = (const int*)d_in[2];
    const float* snorm_n = (const float*)d_in[3];
    const float* embed = (const float*)d_in[5];
    const float* W[3] = {(const float*)d_in[6], (const float*)d_in[11], (const float*)d_in[16]};
    const float* al[3] = {(const float*)d_in[7], (const float*)d_in[12], (const float*)d_in[17]};
    const float* ar[3] = {(const float*)d_in[8], (const float*)d_in[13], (const float*)d_in[18]};
    const float* gamma[3] = {(const float*)d_in[9], (const float*)d_in[14], (const float*)d_in[19]};
    const float* beta[3] = {(const float*)d_in[10], (const float*)d_in[15], (const float*)d_in[20]};
    const float* cls1_w = (const float*)d_in[21];
    const float* cls1_b = (const float*)d_in[22];
    const float* cls2_w = (const float*)d_in[23];
    const float* cls2_b = (const float*)d_in[24];
    float* out = (float*)d_out;

    float *h0, *h1, *feat, *el, *er, *wlr, *bnstat;
    int *deg, *rowptr, *cursor, *csr, *partial, *poff;
    cudaGetSymbolAddress((void**)&h0, g_h0);
    cudaGetSymbolAddress((void**)&h1, g_h1);
    cudaGetSymbolAddress((void**)&feat, g_feat);
    cudaGetSymbolAddress((void**)&el, g_el);
    cudaGetSymbolAddress((void**)&er, g_er);
    cudaGetSymbolAddress((void**)&wlr, g_wlr);
    cudaGetSymbolAddress((void**)&bnstat, g_bnstat);
    cudaGetSymbolAddress((void**)&deg, g_deg);
    cudaGetSymbolAddress((void**)&rowptr, g_rowptr);
    cudaGetSymbolAddress((void**)&cursor, g_cursor);
    cudaGetSymbolAddress((void**)&csr, g_csr);
    cudaGetSymbolAddress((void**)&partial, g_partial);
    cudaGetSymbolAddress((void**)&poff, g_poff);

    static bool attr_done = false;
    if (!attr_done) {
        cudaFuncSetAttribute(k_cls, cudaFuncAttributeMaxDynamicSharedMemorySize, 65536);
        attr_done = true;
    }
    const int GEMM_SMEM = (128 * 40 + 32 * 152 + 8 * 256) * 4;   // 48128
    const int CLS_SMEM = (128 * 36 + 32 * 68 + 128 * 68) * 4;    // 61952
    const int NSCAN = (NN + 255) / 256;  // 196

    // CSR build
    cudaMemsetAsync(deg, 0, NN * sizeof(int), 0);
    k_hist<<<(EE + 255) / 256, 256>>>(dst, deg);
    k_scan1<<<NSCAN, 256>>>(deg, partial);
    k_scan2<<<1, 256>>>(partial, poff, NSCAN);
    k_scan3<<<NSCAN, 256>>>(deg, poff, rowptr, cursor);
    k_fill<<<(EE + 255) / 256, 256>>>(src, dst, cursor, csr);

    float* hin = h0;
    float* hout = h1;
    for (int l = 0; l < 3; l++) {
        k_wlr<<<1, 1024>>>(W[l], al[l], ar[l], wlr);
        cudaMemsetAsync(bnstat, 0, 256 * sizeof(float), 0);
        k_gemm_eler<<<(NN + 127) / 128, 256, GEMM_SMEM>>>(
            hin, (l == 0) ? x : nullptr, embed, W[l], wlr, feat, (float4*)el, (float4*)er);
        if (l == 0) {
            k_agg<false, false><<<NN / 8, 256>>>(
                (const float4*)feat, (const float4*)hin, (const float4*)el,
                (const float4*)er, snorm_n, rowptr, csr, (float4*)hout, bnstat);
        } else {
            k_agg<true, true><<<NN / 8, 256>>>(
                (const float4*)feat, (const float4*)hin, (const float4*)el,
                (const float4*)er, snorm_n, rowptr, csr, (float4*)hout, bnstat);
        }
        k_bnapply<<<(NN * HDIM + 255) / 256, 256>>>(hout, gamma[l], beta[l], bnstat);
        float* tmp = hin; hin = hout; hout = tmp;
    }
    k_cls<<<(NN + 127) / 128, 256, CLS_SMEM>>>(hin, cls1_w, cls1_b, cls2_w, cls2_b, out);
}

// round 3
// speedup vs baseline: 1.1398x; 1.1398x over previous
#include <cuda_runtime.h>
#include <cuda_fp16.h>
#include <mma.h>
using namespace nvcuda;

#define NN 50000
#define EE 850000

// ---------------- scratch (device globals) ----------------------------------
__device__ float  g_h0[NN * 128];
__device__ float  g_h1[NN * 128];
__device__ __half g_feath[NN * 128];
__device__ float  g_el[NN * 4];
__device__ float  g_er[NN * 4];
__device__ int    g_deg[NN];
__device__ int    g_rowptr[NN + 1];
__device__ int    g_cursor[NN];
__device__ int    g_csr[EE];
__device__ int    g_partial[256];
__device__ int    g_poff[256];
__device__ float  g_bnstat[3 * 256];  // per layer: [0:128) sum, [128:256) sumsq

__device__ __forceinline__ float eluf(float x) { return x > 0.f ? x : (__expf(x) - 1.f); }
__device__ __forceinline__ float lrelu(float x) { return x > 0.f ? x : 0.2f * x; }

// ---------------- CSR build --------------------------------------------------
__global__ void k_hist(const int* __restrict__ dst, int* deg) {
    int i = blockIdx.x * blockDim.x + threadIdx.x;
    if (i < EE) atomicAdd(&deg[dst[i]], 1);
}

__device__ __forceinline__ int block_scan_excl(int v, int t) {
    __shared__ int ws[8];
    int lane = t & 31, w = t >> 5;
    int incl = v;
#pragma unroll
    for (int o = 1; o < 32; o <<= 1) {
        int u = __shfl_up_sync(0xffffffffu, incl, o);
        if (lane >= o) incl += u;
    }
    if (lane == 31) ws[w] = incl;
    __syncthreads();
    if (t == 0) {
        int run = 0;
#pragma unroll
        for (int i = 0; i < 8; i++) { int x = ws[i]; ws[i] = run; run += x; }
    }
    __syncthreads();
    return incl - v + ws[w];
}

__global__ void k_scan1(const int* __restrict__ deg, int* __restrict__ partial) {
    __shared__ int ws[8];
    int t = threadIdx.x, idx = blockIdx.x * 256 + t;
    int v = (idx < NN) ? deg[idx] : 0;
#pragma unroll
    for (int o = 16; o > 0; o >>= 1) v += __shfl_xor_sync(0xffffffffu, v, o);
    if ((t & 31) == 0) ws[t >> 5] = v;
    __syncthreads();
    if (t == 0) {
        int s = 0;
#pragma unroll
        for (int i = 0; i < 8; i++) s += ws[i];
        partial[blockIdx.x] = s;
    }
}

__global__ void k_scan2(const int* __restrict__ partial, int* __restrict__ poff, int nblk) {
    int t = threadIdx.x;
    int v = (t < nblk) ? partial[t] : 0;
    int excl = block_scan_excl(v, t);
    if (t < nblk) poff[t] = excl;
}

__global__ void k_scan3(const int* __restrict__ deg, const int* __restrict__ poff,
                        int* __restrict__ rowptr, int* __restrict__ cursor) {
    int t = threadIdx.x, idx = blockIdx.x * 256 + t;
    int v = (idx < NN) ? deg[idx] : 0;
    int excl = block_scan_excl(v, t);
    int res = poff[blockIdx.x] + excl;
    if (idx <= NN) rowptr[idx] = res;
    if (idx < NN) cursor[idx] = res;
}

__global__ void k_fill(const int* __restrict__ src, const int* __restrict__ dst,
                       int* cursor, int* __restrict__ csr) {
    int i = blockIdx.x * blockDim.x + threadIdx.x;
    if (i < EE) {
        int d = dst[i];
        int pos = atomicAdd(&cursor[d], 1);
        csr[pos] = src[i];
    }
}

// ---------------- split-TF32 GEMM: C[N,128]=A[N,128]@W, fp16 out -------------
// L0: A comes from embed[x[row]]; else A = elu(BN_prev(hin)).
template <bool L0>
__global__ void k_gemm(const float* __restrict__ A, const int* __restrict__ xidx,
                       const float* __restrict__ embed, const float* __restrict__ W,
                       const float* __restrict__ stat, const float* __restrict__ gamma,
                       const float* __restrict__ beta, __half* __restrict__ feat) {
    extern __shared__ float sm[];
    float* sAhi = sm;                 // 128 x 40
    float* sAlo = sAhi + 128 * 40;    // 128 x 40
    float* sWhi = sAlo + 128 * 40;    // 32 x 136
    float* sWlo = sWhi + 32 * 136;    // 32 x 136
    __shared__ float sc[128], shf[128];
    int tid = threadIdx.x, warp = tid >> 5;
    int row0 = blockIdx.x * 128;

    if (!L0) {
        if (tid < 128) {
            float mu = stat[tid] * (1.f / NN);
            float var = stat[128 + tid] * (1.f / NN) - mu * mu;
            float r = rsqrtf(var + 1e-5f);
            sc[tid] = gamma[tid] * r;
            shf[tid] = beta[tid] - mu * gamma[tid] * r;
        }
        __syncthreads();
    }

    wmma::fragment<wmma::accumulator, 16, 16, 8, float> fc[8];
#pragma unroll
    for (int i = 0; i < 8; i++) wmma::fill_fragment(fc[i], 0.f);

    for (int kb = 0; kb < 4; kb++) {
        // A tile: 128 rows x 32 k
        for (int p = tid; p < 1024; p += 256) {
            int row = p >> 3, kp = (p & 7) * 4;
            int gr = row0 + row;
            float4 v = make_float4(0.f, 0.f, 0.f, 0.f);
            int c = kb * 32 + kp;
            if (gr < NN) {
                if (L0) v = *(const float4*)&embed[(size_t)xidx[gr] * 128 + c];
                else {
                    v = *(const float4*)&A[(size_t)gr * 128 + c];
                    v.x = eluf(v.x * sc[c] + shf[c]);
                    v.y = eluf(v.y * sc[c + 1] + shf[c + 1]);
                    v.z = eluf(v.z * sc[c + 2] + shf[c + 2]);
                    v.w = eluf(v.w * sc[c + 3] + shf[c + 3]);
                }
            }
            float hx = wmma::__float_to_tf32(v.x), hy = wmma::__float_to_tf32(v.y);
            float hz = wmma::__float_to_tf32(v.z), hw = wmma::__float_to_tf32(v.w);
            float* ph = sAhi + row * 40 + kp;
            float* pl = sAlo + row * 40 + kp;
            ph[0] = hx; ph[1] = hy; ph[2] = hz; ph[3] = hw;
            pl[0] = wmma::__float_to_tf32(v.x - hx);
            pl[1] = wmma::__float_to_tf32(v.y - hy);
            pl[2] = wmma::__float_to_tf32(v.z - hz);
            pl[3] = wmma::__float_to_tf32(v.w - hw);
        }
        // W tile: 32 k x 128 cols
        for (int p = tid; p < 1024; p += 256) {
            int r = p >> 5, cp = (p & 31) * 4;
            float4 v = *(const float4*)&W[(size_t)(kb * 32 + r) * 128 + cp];
            float hx = wmma::__float_to_tf32(v.x), hy = wmma::__float_to_tf32(v.y);
            float hz = wmma::__float_to_tf32(v.z), hw = wmma::__float_to_tf32(v.w);
            float* ph = sWhi + r * 136 + cp;
            float* pl = sWlo + r * 136 + cp;
            ph[0] = hx; ph[1] = hy; ph[2] = hz; ph[3] = hw;
            pl[0] = wmma::__float_to_tf32(v.x - hx);
            pl[1] = wmma::__float_to_tf32(v.y - hy);
            pl[2] = wmma::__float_to_tf32(v.z - hz);
            pl[3] = wmma::__float_to_tf32(v.w - hw);
        }
        __syncthreads();
#pragma unroll
        for (int ks = 0; ks < 4; ks++) {
            wmma::fragment<wmma::matrix_a, 16, 16, 8, wmma::precision::tf32, wmma::row_major> fah, fal;
            wmma::load_matrix_sync(fah, sAhi + (warp * 16) * 40 + ks * 8, 40);
            wmma::load_matrix_sync(fal, sAlo + (warp * 16) * 40 + ks * 8, 40);
#pragma unroll
            for (int ct = 0; ct < 8; ct++) {
                wmma::fragment<wmma::matrix_b, 16, 16, 8, wmma::precision::tf32, wmma::row_major> fbh, fbl;
                wmma::load_matrix_sync(fbh, sWhi + (ks * 8) * 136 + ct * 16, 136);
                wmma::load_matrix_sync(fbl, sWlo + (ks * 8) * 136 + ct * 16, 136);
                wmma::mma_sync(fc[ct], fah, fbh, fc[ct]);
                wmma::mma_sync(fc[ct], fal, fbh, fc[ct]);
                wmma::mma_sync(fc[ct], fah, fbl, fc[ct]);
            }
        }
        __syncthreads();
    }
    // stage fp32 result in smem (reuse tiles), convert to fp16, store
    float* sStage = sm;  // 128 x 136 (17408 floats <= 18944 available)
#pragma unroll
    for (int ct = 0; ct < 8; ct++)
        wmma::store_matrix_sync(sStage + (warp * 16) * 136 + ct * 16, fc[ct], 136,
                                wmma::mem_row_major);
    __syncthreads();
    for (int p = tid; p < 128 * 16; p += 256) {
        int row = p >> 4, c8 = (p & 15) * 8;
        int gr = row0 + row;
        if (gr < NN) {
            const float* s = sStage + row * 136 + c8;
            __half2 h0 = __floats2half2_rn(s[0], s[1]);
            __half2 h1 = __floats2half2_rn(s[2], s[3]);
            __half2 h2 = __floats2half2_rn(s[4], s[5]);
            __half2 h3 = __floats2half2_rn(s[6], s[7]);
            uint4 pack;
            pack.x = *(unsigned*)&h0; pack.y = *(unsigned*)&h1;
            pack.z = *(unsigned*)&h2; pack.w = *(unsigned*)&h3;
            *(uint4*)(feat + (size_t)gr * 128 + c8) = pack;
        }
    }
}

// ---------------- el / er from fp16 feat -------------------------------------
__global__ void k_eler(const __half* __restrict__ feat, const float* __restrict__ al,
                       const float* __restrict__ ar, float* __restrict__ el,
                       float* __restrict__ er) {
    int n = blockIdx.x * 2 + (threadIdx.x >> 7);
    int t = threadIdx.x & 127;
    int w = t >> 5;
    int lane = threadIdx.x & 31;
    float f = __half2float(feat[(size_t)n * 128 + t]);
    float pl = f * al[t];
    float pr = f * ar[t];
#pragma unroll
    for (int o = 16; o > 0; o >>= 1) {
        pl += __shfl_xor_sync(0xffffffffu, pl, o);
        pr += __shfl_xor_sync(0xffffffffu, pr, o);
    }
    if (lane == 0) {
        el[n * 4 + w] = pl;
        er[n * 4 + w] = pr;
    }
}

// ---------------- fused softmax + aggregation + BN stats ---------------------
// RES: residual = elu(BN_prev(hin)); ACT: elu on (rst+res).
template <bool RES, bool ACT>
__global__ void k_agg(const __half* __restrict__ feat, const float* __restrict__ hin,
                      const float4* __restrict__ el4, const float4* __restrict__ er4,
                      const float* __restrict__ snorm, const int* __restrict__ rowptr,
                      const int* __restrict__ csr, float* __restrict__ out,
                      float* __restrict__ bnstat, const float* __restrict__ pstat,
                      const float* __restrict__ pgamma, const float* __restrict__ pbeta) {
    __shared__ int   s_sj[8][32];
    __shared__ float s_a[8][32][4];
    __shared__ float bs[1024];
    __shared__ float bq[1024];
    __shared__ float psc[128], psh[128];
    int warp = threadIdx.x >> 5;
    int lane = threadIdx.x & 31;
    int node = blockIdx.x * 8 + warp;  // NN % 8 == 0
    if (RES) {
        int t = threadIdx.x;
        if (t < 128) {
            float mu = pstat[t] * (1.f / NN);
            float var = pstat[128 + t] * (1.f / NN) - mu * mu;
            float r = rsqrtf(var + 1e-5f);
            psc[t] = pgamma[t] * r;
            psh[t] = pbeta[t] - mu * pgamma[t] * r;
        }
        __syncthreads();
    }
    int start = rowptr[node], end = rowptr[node + 1];
    int deg = end - start;
    float4 er = er4[node];
    int hl = lane >> 3;
    int c0 = lane * 4;

    float4 acc = make_float4(0.f, 0.f, 0.f, 0.f);
    if (RES) {
        float4 h = *(const float4*)&hin[(size_t)node * 128 + c0];
        acc.x = eluf(h.x * psc[c0] + psh[c0]);
        acc.y = eluf(h.y * psc[c0 + 1] + psh[c0 + 1]);
        acc.z = eluf(h.z * psc[c0 + 2] + psh[c0 + 2]);
        acc.w = eluf(h.w * psc[c0 + 3] + psh[c0 + 3]);
    }

    if (deg <= 32) {
        bool on = lane < deg;
        int s = on ? csr[start + lane] : 0;
        float4 v = make_float4(-3e38f, -3e38f, -3e38f, -3e38f);
        if (on) {
            float4 e = el4[s];
            v.x = lrelu(e.x + er.x); v.y = lrelu(e.y + er.y);
            v.z = lrelu(e.z + er.z); v.w = lrelu(e.w + er.w);
        }
        float4 mx = v;
#pragma unroll
        for (int o = 16; o > 0; o >>= 1) {
            mx.x = fmaxf(mx.x, __shfl_xor_sync(0xffffffffu, mx.x, o));
            mx.y = fmaxf(mx.y, __shfl_xor_sync(0xffffffffu, mx.y, o));
            mx.z = fmaxf(mx.z, __shfl_xor_sync(0xffffffffu, mx.z, o));
            mx.w = fmaxf(mx.w, __shfl_xor_sync(0xffffffffu, mx.w, o));
        }
        float4 ex = make_float4(0.f, 0.f, 0.f, 0.f);
        if (on) {
            ex.x = __expf(v.x - mx.x); ex.y = __expf(v.y - mx.y);
            ex.z = __expf(v.z - mx.z); ex.w = __expf(v.w - mx.w);
        }
        float4 sm4 = ex;
#pragma unroll
        for (int o = 16; o > 0; o >>= 1) {
            sm4.x += __shfl_xor_sync(0xffffffffu, sm4.x, o);
            sm4.y += __shfl_xor_sync(0xffffffffu, sm4.y, o);
            sm4.z += __shfl_xor_sync(0xffffffffu, sm4.z, o);
            sm4.w += __shfl_xor_sync(0xffffffffu, sm4.w, o);
        }
        s_sj[warp][lane] = s;
        float4 aex = make_float4(ex.x / sm4.x, ex.y / sm4.y, ex.z / sm4.z, ex.w / sm4.w);
        *(float4*)&s_a[warp][lane][0] = aex;
        __syncwarp();
        for (int j = 0; j < deg; j++) {
            int sj = s_sj[warp][j];
            float a = s_a[warp][j][hl];
            uint2 raw = *(const uint2*)(feat + (size_t)sj * 128 + c0);
            float2 f01 = __half22float2(*(__half2*)&raw.x);
            float2 f23 = __half22float2(*(__half2*)&raw.y);
            acc.x += f01.x * a; acc.y += f01.y * a;
            acc.z += f23.x * a; acc.w += f23.y * a;
        }
    } else {
        float mx0 = -3e38f, mx1 = -3e38f, mx2 = -3e38f, mx3 = -3e38f;
        for (int k = start + lane; k < end; k += 32) {
            int s = csr[k];
            float4 e = el4[s];
            mx0 = fmaxf(mx0, lrelu(e.x + er.x)); mx1 = fmaxf(mx1, lrelu(e.y + er.y));
            mx2 = fmaxf(mx2, lrelu(e.z + er.z)); mx3 = fmaxf(mx3, lrelu(e.w + er.w));
        }
#pragma unroll
        for (int o = 16; o > 0; o >>= 1) {
            mx0 = fmaxf(mx0, __shfl_xor_sync(0xffffffffu, mx0, o));
            mx1 = fmaxf(mx1, __shfl_xor_sync(0xffffffffu, mx1, o));
            mx2 = fmaxf(mx2, __shfl_xor_sync(0xffffffffu, mx2, o));
            mx3 = fmaxf(mx3, __shfl_xor_sync(0xffffffffu, mx3, o));
        }
        float s0 = 0.f, s1 = 0.f, s2 = 0.f, s3 = 0.f;
        for (int k = start + lane; k < end; k += 32) {
            int s = csr[k];
            float4 e = el4[s];
            s0 += __expf(lrelu(e.x + er.x) - mx0);
            s1 += __expf(lrelu(e.y + er.y) - mx1);
            s2 += __expf(lrelu(e.z + er.z) - mx2);
            s3 += __expf(lrelu(e.w + er.w) - mx3);
        }
#pragma unroll
        for (int o = 16; o > 0; o >>= 1) {
            s0 += __shfl_xor_sync(0xffffffffu, s0, o);
            s1 += __shfl_xor_sync(0xffffffffu, s1, o);
            s2 += __shfl_xor_sync(0xffffffffu, s2, o);
            s3 += __shfl_xor_sync(0xffffffffu, s3, o);
        }
        float mxh = hl == 0 ? mx0 : hl == 1 ? mx1 : hl == 2 ? mx2 : mx3;
        float invh = 1.f / (hl == 0 ? s0 : hl == 1 ? s1 : hl == 2 ? s2 : s3);
        float erh = hl == 0 ? er.x : hl == 1 ? er.y : hl == 2 ? er.z : er.w;
        for (int k = start; k < end; k++) {
            int s = csr[k];
            float4 e = el4[s];
            float ev = hl == 0 ? e.x : hl == 1 ? e.y : hl == 2 ? e.z : e.w;
            float a = __expf(lrelu(ev + erh) - mxh) * invh;
            uint2 raw = *(const uint2*)(feat + (size_t)s * 128 + c0);
            float2 f01 = __half22float2(*(__half2*)&raw.x);
            float2 f23 = __half22float2(*(__half2*)&raw.y);
            acc.x += f01.x * a; acc.y += f01.y * a;
            acc.z += f23.x * a; acc.w += f23.y * a;
        }
    }
    if (ACT) {
        acc.x = eluf(acc.x); acc.y = eluf(acc.y);
        acc.z = eluf(acc.z); acc.w = eluf(acc.w);
    }
    float sn = snorm[node];
    acc.x *= sn; acc.y *= sn; acc.z *= sn; acc.w *= sn;
    *(float4*)&out[(size_t)node * 128 + c0] = acc;

    ((float4*)bs)[warp * 32 + lane] = acc;
    ((float4*)bq)[warp * 32 + lane] =
        make_float4(acc.x * acc.x, acc.y * acc.y, acc.z * acc.z, acc.w * acc.w);
    __syncthreads();
    int t = threadIdx.x;
    if (t < 128) {
        float s = 0.f, q = 0.f;
#pragma unroll
        for (int w = 0; w < 8; w++) { s += bs[w * 128 + t]; q += bq[w * 128 + t]; }
        atomicAdd(&bnstat[t], s);
        atomicAdd(&bnstat[128 + t], q);
    }
}

// ---------------- fused classifier (BN2+elu on load) -------------------------
__global__ void k_cls(const float* __restrict__ H, const float* __restrict__ w1,
                      const float* __restrict__ b1, const float* __restrict__ w2,
                      const float* __restrict__ b2, const float* __restrict__ stat,
                      const float* __restrict__ gamma, const float* __restrict__ beta,
                      float* __restrict__ out) {
    __shared__ float Ws[32][64];
    __shared__ float As[64][33];
    __shared__ float Ts[64][65];
    __shared__ float sc[128], shf[128];
    int tid = threadIdx.x, tx = tid & 31, ty = tid >> 5;
    int row0 = blockIdx.x * 64;
    if (tid < 128) {
        float mu = stat[tid] * (1.f / NN);
        float var = stat[128 + tid] * (1.f / NN) - mu * mu;
        float r = rsqrtf(var + 1e-5f);
        sc[tid] = gamma[tid] * r;
        shf[tid] = beta[tid] - mu * gamma[tid] * r;
    }
    __syncthreads();
    float acc[8][2];
#pragma unroll
    for (int r = 0; r < 8; r++) { acc[r][0] = 0.f; acc[r][1] = 0.f; }

    for (int kb = 0; kb < 4; kb++) {
        for (int i = tid; i < 2048; i += 256) {
            int kk = i >> 6, j = i & 63;
            Ws[kk][j] = w1[(kb * 32 + kk) * 64 + j];
        }
        for (int i = tid; i < 2048; i += 256) {
            int r = i >> 5, kk = i & 31;
            int gr = row0 + r;
            int c = kb * 32 + kk;
            float v = 0.f;
            if (gr < NN) v = eluf(H[(size_t)gr * 128 + c] * sc[c] + shf[c]);
            As[r][kk] = v;
        }
        __syncthreads();
#pragma unroll
        for (int kk = 0; kk < 32; kk++) {
            float b0 = Ws[kk][tx], b1v = Ws[kk][tx + 32];
#pragma unroll
            for (int r = 0; r < 8; r++) {
                float a = As[ty + 8 * r][kk];
                acc[r][0] += a * b0;
                acc[r][1] += a * b1v;
            }
        }
        __syncthreads();
    }
    float bb0 = b1[tx], bb1 = b1[tx + 32];
#pragma unroll
    for (int r = 0; r < 8; r++) {
        float t0 = acc[r][0] + bb0;
        float t1 = acc[r][1] + bb1;
        Ts[ty + 8 * r][tx] = t0 > 0.f ? t0 : 0.f;
        Ts[ty + 8 * r][tx + 32] = t1 > 0.f ? t1 : 0.f;
    }
    __syncthreads();
    if (tid < 128) {
        int row = tid >> 1, o = tid & 1;
        float s = b2[o];
        for (int k = 0; k < 64; k++) s += Ts[row][k] * w2[k * 2 + o];
        int gr = row0 + row;
        if (gr < NN) out[(size_t)gr * 2 + o] = s;
    }
}

// ---------------- host orchestration -----------------------------------------
extern "C" void kernel_launch(void* const* d_in, const int* in_sizes, int n_in,
                              void* d_out, int out_size) {
    const int* x = (const int*)d_in[0];
    const int* src = (const int*)d_in[1];
    const int* dst = (const int*)d_in[2];
    const float* snorm_n = (const float*)d_in[3];
    const float* embed = (const float*)d_in[5];
    const float* W[3] = {(const float*)d_in[6], (const float*)d_in[11], (const float*)d_in[16]};
    const float* al[3] = {(const float*)d_in[7], (const float*)d_in[12], (const float*)d_in[17]};
    const float* ar[3] = {(const float*)d_in[8], (const float*)d_in[13], (const float*)d_in[18]};
    const float* gamma[3] = {(const float*)d_in[9], (const float*)d_in[14], (const float*)d_in[19]};
    const float* beta[3] = {(const float*)d_in[10], (const float*)d_in[15], (const float*)d_in[20]};
    const float* cls1_w = (const float*)d_in[21];
    const float* cls1_b = (const float*)d_in[22];
    const float* cls2_w = (const float*)d_in[23];
    const float* cls2_b = (const float*)d_in[24];
    float* out = (float*)d_out;

    float *h0, *h1, *el, *er, *bnstat;
    __half* feath;
    int *deg, *rowptr, *cursor, *csr, *partial, *poff;
    cudaGetSymbolAddress((void**)&h0, g_h0);
    cudaGetSymbolAddress((void**)&h1, g_h1);
    cudaGetSymbolAddress((void**)&feath, g_feath);
    cudaGetSymbolAddress((void**)&el, g_el);
    cudaGetSymbolAddress((void**)&er, g_er);
    cudaGetSymbolAddress((void**)&bnstat, g_bnstat);
    cudaGetSymbolAddress((void**)&deg, g_deg);
    cudaGetSymbolAddress((void**)&rowptr, g_rowptr);
    cudaGetSymbolAddress((void**)&cursor, g_cursor);
    cudaGetSymbolAddress((void**)&csr, g_csr);
    cudaGetSymbolAddress((void**)&partial, g_partial);
    cudaGetSymbolAddress((void**)&poff, g_poff);

    const int GEMM_SMEM = (128 * 40 * 2 + 32 * 136 * 2) * 4;  // 75776
    static bool attr_done = false;
    if (!attr_done) {
        cudaFuncSetAttribute(k_gemm<true>, cudaFuncAttributeMaxDynamicSharedMemorySize, GEMM_SMEM);
        cudaFuncSetAttribute(k_gemm<false>, cudaFuncAttributeMaxDynamicSharedMemorySize, GEMM_SMEM);
        attr_done = true;
    }
    const int NSCAN = (NN + 255) / 256;  // 196
    const int GB = (NN + 127) / 128;     // 391

    cudaMemsetAsync(deg, 0, NN * sizeof(int), 0);
    cudaMemsetAsync(bnstat, 0, 3 * 256 * sizeof(float), 0);

    // kernel launch order chosen so gemm0 is the 4th kernel (ncu capture slot)
    k_hist<<<(EE + 255) / 256, 256>>>(dst, deg);                       // 1
    k_scan1<<<NSCAN, 256>>>(deg, partial);                             // 2
    k_scan2<<<1, 256>>>(partial, poff, NSCAN);                         // 3
    k_gemm<true><<<GB, 256, GEMM_SMEM>>>(nullptr, x, embed, W[0],      // 4
                                         nullptr, nullptr, nullptr, feath);
    k_scan3<<<NSCAN, 256>>>(deg, poff, rowptr, cursor);                // 5
    k_fill<<<(EE + 255) / 256, 256>>>(src, dst, cursor, csr);          // 6
    k_eler<<<NN / 2, 256>>>(feath, al[0], ar[0], el, er);              // 7
    k_agg<false, false><<<NN / 8, 256>>>(feath, nullptr, (const float4*)el,
                                         (const float4*)er, snorm_n, rowptr, csr,
                                         h0, &bnstat[0], nullptr, nullptr, nullptr);

    // layer 1
    k_gemm<false><<<GB, 256, GEMM_SMEM>>>(h0, nullptr, nullptr, W[1],
                                          &bnstat[0], gamma[0], beta[0], feath);
    k_eler<<<NN / 2, 256>>>(feath, al[1], ar[1], el, er);
    k_agg<true, true><<<NN / 8, 256>>>(feath, h0, (const float4*)el,
                                       (const float4*)er, snorm_n, rowptr, csr,
                                       h1, &bnstat[256], &bnstat[0], gamma[0], beta[0]);
    // layer 2
    k_gemm<false><<<GB, 256, GEMM_SMEM>>>(h1, nullptr, nullptr, W[2],
                                          &bnstat[256], gamma[1], beta[1], feath);
    k_eler<<<NN / 2, 256>>>(feath, al[2], ar[2], el, er);
    k_agg<true, true><<<NN / 8, 256>>>(feath, h1, (const float4*)el,
                                       (const float4*)er, snorm_n, rowptr, csr,
                                       h0, &bnstat[512], &bnstat[256], gamma[1], beta[1]);
    // classifier
    k_cls<<<(NN + 63) / 64, 256>>>(h0, cls1_w, cls1_b, cls2_w, cls2_b,
                                   &bnstat[512], gamma[2], beta[2], out);
}

// round 4
// speedup vs baseline: 1.6995x; 1.4910x over previous
#include <cuda_runtime.h>
#include <cuda_fp16.h>
#include <mma.h>
using namespace nvcuda;

#define NN 50000
#define EE 850000

// ---------------- scratch (device globals) ----------------------------------
__device__ float  g_h0[NN * 128];
__device__ float  g_h1[NN * 128];
__device__ __half g_feath[NN * 128];
__device__ float  g_el[NN * 4];
__device__ float  g_er[NN * 4];
__device__ int    g_deg[NN];
__device__ int    g_rowptr[NN + 1];
__device__ int    g_cursor[NN];
__device__ int    g_csr[EE];
__device__ int    g_partial[256];
__device__ int    g_poff[256];
__device__ float  g_bnstat[3 * 256];

__device__ __forceinline__ float eluf(float x) { return x > 0.f ? x : (__expf(x) - 1.f); }
__device__ __forceinline__ float lrelu(float x) { return x > 0.f ? x : 0.2f * x; }

__device__ __forceinline__ void split2h(float v, __half& hi, __half& lo) {
    hi = __float2half_rn(v);
    lo = __float2half_rn(v - __half2float(hi));
}

// ---------------- CSR build --------------------------------------------------
__global__ void k_hist(const int* __restrict__ dst, int* deg) {
    int i = blockIdx.x * blockDim.x + threadIdx.x;
    if (i < EE) atomicAdd(&deg[dst[i]], 1);
}

__device__ __forceinline__ int block_scan_excl(int v, int t) {
    __shared__ int ws[8];
    int lane = t & 31, w = t >> 5;
    int incl = v;
#pragma unroll
    for (int o = 1; o < 32; o <<= 1) {
        int u = __shfl_up_sync(0xffffffffu, incl, o);
        if (lane >= o) incl += u;
    }
    if (lane == 31) ws[w] = incl;
    __syncthreads();
    if (t == 0) {
        int run = 0;
#pragma unroll
        for (int i = 0; i < 8; i++) { int x = ws[i]; ws[i] = run; run += x; }
    }
    __syncthreads();
    return incl - v + ws[w];
}

__global__ void k_scan1(const int* __restrict__ deg, int* __restrict__ partial) {
    __shared__ int ws[8];
    int t = threadIdx.x, idx = blockIdx.x * 256 + t;
    int v = (idx < NN) ? deg[idx] : 0;
#pragma unroll
    for (int o = 16; o > 0; o >>= 1) v += __shfl_xor_sync(0xffffffffu, v, o);
    if ((t & 31) == 0) ws[t >> 5] = v;
    __syncthreads();
    if (t == 0) {
        int s = 0;
#pragma unroll
        for (int i = 0; i < 8; i++) s += ws[i];
        partial[blockIdx.x] = s;
    }
}

__global__ void k_scan2(const int* __restrict__ partial, int* __restrict__ poff, int nblk) {
    int t = threadIdx.x;
    int v = (t < nblk) ? partial[t] : 0;
    int excl = block_scan_excl(v, t);
    if (t < nblk) poff[t] = excl;
}

__global__ void k_scan3(const int* __restrict__ deg, const int* __restrict__ poff,
                        int* __restrict__ rowptr, int* __restrict__ cursor) {
    int t = threadIdx.x, idx = blockIdx.x * 256 + t;
    int v = (idx < NN) ? deg[idx] : 0;
    int excl = block_scan_excl(v, t);
    int res = poff[blockIdx.x] + excl;
    if (idx <= NN) rowptr[idx] = res;
    if (idx < NN) cursor[idx] = res;
}

__global__ void k_fill(const int* __restrict__ src, const int* __restrict__ dst,
                       int* cursor, int* __restrict__ csr) {
    int i = blockIdx.x * blockDim.x + threadIdx.x;
    if (i < EE) {
        int d = dst[i];
        int pos = atomicAdd(&cursor[d], 1);
        csr[pos] = src[i];
    }
}

// ---------------- split-FP16 HMMA GEMM: C[N,128]=A[N,128]@W ------------------
// 64 rows/block, 256 threads. W resident in smem (hi/lo), single K pass.
// L0: A = embed[x[row]]; else A = elu(BN_prev(hin)).
template <bool L0>
__global__ void k_gemm(const float* __restrict__ A, const int* __restrict__ xidx,
                       const float* __restrict__ embed, const float* __restrict__ W,
                       const float* __restrict__ stat, const float* __restrict__ gamma,
                       const float* __restrict__ beta, __half* __restrict__ feat) {
    extern __shared__ __half smh[];
    __half* sWhi = smh;                    // 128 x 136
    __half* sWlo = sWhi + 128 * 136;       // 128 x 136
    __half* sAhi = sWlo + 128 * 136;       // 64 x 136
    __half* sAlo = sAhi + 64 * 136;        // 64 x 136
    __shared__ float sc[128], shf[128];
    int tid = threadIdx.x, warp = tid >> 5;
    int row0 = blockIdx.x * 64;

    if (!L0) {
        if (tid < 128) {
            float mu = stat[tid] * (1.f / NN);
            float var = stat[128 + tid] * (1.f / NN) - mu * mu;
            float r = rsqrtf(var + 1e-5f);
            sc[tid] = gamma[tid] * r;
            shf[tid] = beta[tid] - mu * gamma[tid] * r;
        }
        __syncthreads();
    }

    // load + split W (once)
    for (int p = tid; p < 4096; p += 256) {
        int r = p >> 5, c = (p & 31) * 4;
        float4 v = *(const float4*)&W[(size_t)r * 128 + c];
        split2h(v.x, sWhi[r * 136 + c], sWlo[r * 136 + c]);
        split2h(v.y, sWhi[r * 136 + c + 1], sWlo[r * 136 + c + 1]);
        split2h(v.z, sWhi[r * 136 + c + 2], sWlo[r * 136 + c + 2]);
        split2h(v.w, sWhi[r * 136 + c + 3], sWlo[r * 136 + c + 3]);
    }
    // load + (BN/elu) + split A tile
    for (int p = tid; p < 2048; p += 256) {
        int row = p >> 5, c = (p & 31) * 4;
        int gr = row0 + row;
        float4 v = make_float4(0.f, 0.f, 0.f, 0.f);
        if (gr < NN) {
            if (L0) v = *(const float4*)&embed[(size_t)xidx[gr] * 128 + c];
            else {
                v = *(const float4*)&A[(size_t)gr * 128 + c];
                v.x = eluf(v.x * sc[c] + shf[c]);
                v.y = eluf(v.y * sc[c + 1] + shf[c + 1]);
                v.z = eluf(v.z * sc[c + 2] + shf[c + 2]);
                v.w = eluf(v.w * sc[c + 3] + shf[c + 3]);
            }
        }
        split2h(v.x, sAhi[row * 136 + c], sAlo[row * 136 + c]);
        split2h(v.y, sAhi[row * 136 + c + 1], sAlo[row * 136 + c + 1]);
        split2h(v.z, sAhi[row * 136 + c + 2], sAlo[row * 136 + c + 2]);
        split2h(v.w, sAhi[row * 136 + c + 3], sAlo[row * 136 + c + 3]);
    }
    __syncthreads();

    int mrow = (warp & 3) * 16;
    int ncol = (warp >> 2) * 64;
    wmma::fragment<wmma::accumulator, 16, 16, 16, float> fc[4];
#pragma unroll
    for (int i = 0; i < 4; i++) wmma::fill_fragment(fc[i], 0.f);

#pragma unroll
    for (int ks = 0; ks < 8; ks++) {
        wmma::fragment<wmma::matrix_a, 16, 16, 16, __half, wmma::row_major> fah, fal;
        wmma::load_matrix_sync(fah, sAhi + mrow * 136 + ks * 16, 136);
        wmma::load_matrix_sync(fal, sAlo + mrow * 136 + ks * 16, 136);
#pragma unroll
        for (int ct = 0; ct < 4; ct++) {
            wmma::fragment<wmma::matrix_b, 16, 16, 16, __half, wmma::row_major> fbh, fbl;
            wmma::load_matrix_sync(fbh, sWhi + (ks * 16) * 136 + ncol + ct * 16, 136);
            wmma::load_matrix_sync(fbl, sWlo + (ks * 16) * 136 + ncol + ct * 16, 136);
            wmma::mma_sync(fc[ct], fah, fbh, fc[ct]);
            wmma::mma_sync(fc[ct], fal, fbh, fc[ct]);
            wmma::mma_sync(fc[ct], fah, fbl, fc[ct]);
        }
    }
    __syncthreads();
    // stage fp32 in smem (reuse A region: 64*136 floats = exactly sAhi+sAlo)
    float* stage = (float*)sAhi;
#pragma unroll
    for (int ct = 0; ct < 4; ct++)
        wmma::store_matrix_sync(stage + mrow * 136 + ncol + ct * 16, fc[ct], 136,
                                wmma::mem_row_major);
    __syncthreads();
    for (int p = tid; p < 1024; p += 256) {
        int row = p >> 4, c8 = (p & 15) * 8;
        int gr = row0 + row;
        if (gr < NN) {
            const float* s = stage + row * 136 + c8;
            __half2 h0 = __floats2half2_rn(s[0], s[1]);
            __half2 h1 = __floats2half2_rn(s[2], s[3]);
            __half2 h2 = __floats2half2_rn(s[4], s[5]);
            __half2 h3 = __floats2half2_rn(s[6], s[7]);
            uint4 pack;
            pack.x = *(unsigned*)&h0; pack.y = *(unsigned*)&h1;
            pack.z = *(unsigned*)&h2; pack.w = *(unsigned*)&h3;
            *(uint4*)(feat + (size_t)gr * 128 + c8) = pack;
        }
    }
}

// ---------------- el / er from fp16 feat -------------------------------------
__global__ void k_eler(const __half* __restrict__ feat, const float* __restrict__ al,
                       const float* __restrict__ ar, float* __restrict__ el,
                       float* __restrict__ er) {
    int n = blockIdx.x * 2 + (threadIdx.x >> 7);
    int t = threadIdx.x & 127;
    int w = t >> 5;
    int lane = threadIdx.x & 31;
    float f = __half2float(feat[(size_t)n * 128 + t]);
    float pl = f * al[t];
    float pr = f * ar[t];
#pragma unroll
    for (int o = 16; o > 0; o >>= 1) {
        pl += __shfl_xor_sync(0xffffffffu, pl, o);
        pr += __shfl_xor_sync(0xffffffffu, pr, o);
    }
    if (lane == 0) {
        el[n * 4 + w] = pl;
        er[n * 4 + w] = pr;
    }
}

// ---------------- fused softmax + aggregation + BN stats ---------------------
template <bool RES, bool ACT>
__global__ void k_agg(const __half* __restrict__ feat, const float* __restrict__ hin,
                      const float4* __restrict__ el4, const float4* __restrict__ er4,
                      const float* __restrict__ snorm, const int* __restrict__ rowptr,
                      const int* __restrict__ csr, float* __restrict__ out,
                      float* __restrict__ bnstat, const float* __restrict__ pstat,
                      const float* __restrict__ pgamma, const float* __restrict__ pbeta) {
    __shared__ int   s_sj[8][32];
    __shared__ float s_a[8][32][4];
    __shared__ float bs[1024];
    __shared__ float bq[1024];
    __shared__ float psc[128], psh[128];
    int warp = threadIdx.x >> 5;
    int lane = threadIdx.x & 31;
    int node = blockIdx.x * 8 + warp;
    if (RES) {
        int t = threadIdx.x;
        if (t < 128) {
            float mu = pstat[t] * (1.f / NN);
            float var = pstat[128 + t] * (1.f / NN) - mu * mu;
            float r = rsqrtf(var + 1e-5f);
            psc[t] = pgamma[t] * r;
            psh[t] = pbeta[t] - mu * pgamma[t] * r;
        }
        __syncthreads();
    }
    int start = rowptr[node], end = rowptr[node + 1];
    int deg = end - start;
    float4 er = er4[node];
    int hl = lane >> 3;
    int c0 = lane * 4;

    float4 acc = make_float4(0.f, 0.f, 0.f, 0.f);
    if (RES) {
        float4 h = *(const float4*)&hin[(size_t)node * 128 + c0];
        acc.x = eluf(h.x * psc[c0] + psh[c0]);
        acc.y = eluf(h.y * psc[c0 + 1] + psh[c0 + 1]);
        acc.z = eluf(h.z * psc[c0 + 2] + psh[c0 + 2]);
        acc.w = eluf(h.w * psc[c0 + 3] + psh[c0 + 3]);
    }

    if (deg <= 32) {
        bool on = lane < deg;
        int s = on ? csr[start + lane] : 0;
        float4 v = make_float4(-3e38f, -3e38f, -3e38f, -3e38f);
        if (on) {
            float4 e = el4[s];
            v.x = lrelu(e.x + er.x); v.y = lrelu(e.y + er.y);
            v.z = lrelu(e.z + er.z); v.w = lrelu(e.w + er.w);
        }
        float4 mx = v;
#pragma unroll
        for (int o = 16; o > 0; o >>= 1) {
            mx.x = fmaxf(mx.x, __shfl_xor_sync(0xffffffffu, mx.x, o));
            mx.y = fmaxf(mx.y, __shfl_xor_sync(0xffffffffu, mx.y, o));
            mx.z = fmaxf(mx.z, __shfl_xor_sync(0xffffffffu, mx.z, o));
            mx.w = fmaxf(mx.w, __shfl_xor_sync(0xffffffffu, mx.w, o));
        }
        float4 ex = make_float4(0.f, 0.f, 0.f, 0.f);
        if (on) {
            ex.x = __expf(v.x - mx.x); ex.y = __expf(v.y - mx.y);
            ex.z = __expf(v.z - mx.z); ex.w = __expf(v.w - mx.w);
        }
        float4 sm4 = ex;
#pragma unroll
        for (int o = 16; o > 0; o >>= 1) {
            sm4.x += __shfl_xor_sync(0xffffffffu, sm4.x, o);
            sm4.y += __shfl_xor_sync(0xffffffffu, sm4.y, o);
            sm4.z += __shfl_xor_sync(0xffffffffu, sm4.z, o);
            sm4.w += __shfl_xor_sync(0xffffffffu, sm4.w, o);
        }
        s_sj[warp][lane] = s;
        float4 aex = make_float4(ex.x / sm4.x, ex.y / sm4.y, ex.z / sm4.z, ex.w / sm4.w);
        *(float4*)&s_a[warp][lane][0] = aex;
        __syncwarp();
        for (int j = 0; j < deg; j++) {
            int sj = s_sj[warp][j];
            float a = s_a[warp][j][hl];
            uint2 raw = *(const uint2*)(feat + (size_t)sj * 128 + c0);
            float2 f01 = __half22float2(*(__half2*)&raw.x);
            float2 f23 = __half22float2(*(__half2*)&raw.y);
            acc.x += f01.x * a; acc.y += f01.y * a;
            acc.z += f23.x * a; acc.w += f23.y * a;
        }
    } else {
        float mx0 = -3e38f, mx1 = -3e38f, mx2 = -3e38f, mx3 = -3e38f;
        for (int k = start + lane; k < end; k += 32) {
            int s = csr[k];
            float4 e = el4[s];
            mx0 = fmaxf(mx0, lrelu(e.x + er.x)); mx1 = fmaxf(mx1, lrelu(e.y + er.y));
            mx2 = fmaxf(mx2, lrelu(e.z + er.z)); mx3 = fmaxf(mx3, lrelu(e.w + er.w));
        }
#pragma unroll
        for (int o = 16; o > 0; o >>= 1) {
            mx0 = fmaxf(mx0, __shfl_xor_sync(0xffffffffu, mx0, o));
            mx1 = fmaxf(mx1, __shfl_xor_sync(0xffffffffu, mx1, o));
            mx2 = fmaxf(mx2, __shfl_xor_sync(0xffffffffu, mx2, o));
            mx3 = fmaxf(mx3, __shfl_xor_sync(0xffffffffu, mx3, o));
        }
        float s0 = 0.f, s1 = 0.f, s2 = 0.f, s3 = 0.f;
        for (int k = start + lane; k < end; k += 32) {
            int s = csr[k];
            float4 e = el4[s];
            s0 += __expf(lrelu(e.x + er.x) - mx0);
            s1 += __expf(lrelu(e.y + er.y) - mx1);
            s2 += __expf(lrelu(e.z + er.z) - mx2);
            s3 += __expf(lrelu(e.w + er.w) - mx3);
        }
#pragma unroll
        for (int o = 16; o > 0; o >>= 1) {
            s0 += __shfl_xor_sync(0xffffffffu, s0, o);
            s1 += __shfl_xor_sync(0xffffffffu, s1, o);
            s2 += __shfl_xor_sync(0xffffffffu, s2, o);
            s3 += __shfl_xor_sync(0xffffffffu, s3, o);
        }
        float mxh = hl == 0 ? mx0 : hl == 1 ? mx1 : hl == 2 ? mx2 : mx3;
        float invh = 1.f / (hl == 0 ? s0 : hl == 1 ? s1 : hl == 2 ? s2 : s3);
        float erh = hl == 0 ? er.x : hl == 1 ? er.y : hl == 2 ? er.z : er.w;
        for (int k = start; k < end; k++) {
            int s = csr[k];
            float4 e = el4[s];
            float ev = hl == 0 ? e.x : hl == 1 ? e.y : hl == 2 ? e.z : e.w;
            float a = __expf(lrelu(ev + erh) - mxh) * invh;
            uint2 raw = *(const uint2*)(feat + (size_t)s * 128 + c0);
            float2 f01 = __half22float2(*(__half2*)&raw.x);
            float2 f23 = __half22float2(*(__half2*)&raw.y);
            acc.x += f01.x * a; acc.y += f01.y * a;
            acc.z += f23.x * a; acc.w += f23.y * a;
        }
    }
    if (ACT) {
        acc.x = eluf(acc.x); acc.y = eluf(acc.y);
        acc.z = eluf(acc.z); acc.w = eluf(acc.w);
    }
    float sn = snorm[node];
    acc.x *= sn; acc.y *= sn; acc.z *= sn; acc.w *= sn;
    *(float4*)&out[(size_t)node * 128 + c0] = acc;

    ((float4*)bs)[warp * 32 + lane] = acc;
    ((float4*)bq)[warp * 32 + lane] =
        make_float4(acc.x * acc.x, acc.y * acc.y, acc.z * acc.z, acc.w * acc.w);
    __syncthreads();
    int t = threadIdx.x;
    if (t < 128) {
        float s = 0.f, q = 0.f;
#pragma unroll
        for (int w = 0; w < 8; w++) { s += bs[w * 128 + t]; q += bq[w * 128 + t]; }
        atomicAdd(&bnstat[t], s);
        atomicAdd(&bnstat[128 + t], q);
    }
}

// ---------------- classifier: split-fp16 HMMA 128->64, then 64->2 ------------
__global__ void k_cls(const float* __restrict__ H, const float* __restrict__ w1,
                      const float* __restrict__ b1, const float* __restrict__ w2,
                      const float* __restrict__ b2, const float* __restrict__ stat,
                      const float* __restrict__ gamma, const float* __restrict__ beta,
                      float* __restrict__ out) {
    extern __shared__ __half smh[];
    __half* sWhi = smh;                  // 128 x 72
    __half* sWlo = sWhi + 128 * 72;      // 128 x 72
    __half* sAhi = sWlo + 128 * 72;      // 64 x 136
    __half* sAlo = sAhi + 64 * 136;      // 64 x 136
    __shared__ float sc[128], shf[128];
    int tid = threadIdx.x, warp = tid >> 5;
    int row0 = blockIdx.x * 64;
    if (tid < 128) {
        float mu = stat[tid] * (1.f / NN);
        float var = stat[128 + tid] * (1.f / NN) - mu * mu;
        float r = rsqrtf(var + 1e-5f);
        sc[tid] = gamma[tid] * r;
        shf[tid] = beta[tid] - mu * gamma[tid] * r;
    }
    __syncthreads();

    for (int p = tid; p < 2048; p += 256) {
        int r = p >> 4, c = (p & 15) * 4;
        float4 v = *(const float4*)&w1[(size_t)r * 64 + c];
        split2h(v.x, sWhi[r * 72 + c], sWlo[r * 72 + c]);
        split2h(v.y, sWhi[r * 72 + c + 1], sWlo[r * 72 + c + 1]);
        split2h(v.z, sWhi[r * 72 + c + 2], sWlo[r * 72 + c + 2]);
        split2h(v.w, sWhi[r * 72 + c + 3], sWlo[r * 72 + c + 3]);
    }
    for (int p = tid; p < 2048; p += 256) {
        int row = p >> 5, c = (p & 31) * 4;
        int gr = row0 + row;
        float4 v = make_float4(0.f, 0.f, 0.f, 0.f);
        if (gr < NN) {
            v = *(const float4*)&H[(size_t)gr * 128 + c];
            v.x = eluf(v.x * sc[c] + shf[c]);
            v.y = eluf(v.y * sc[c + 1] + shf[c + 1]);
            v.z = eluf(v.z * sc[c + 2] + shf[c + 2]);
            v.w = eluf(v.w * sc[c + 3] + shf[c + 3]);
        }
        split2h(v.x, sAhi[row * 136 + c], sAlo[row * 136 + c]);
        split2h(v.y, sAhi[row * 136 + c + 1], sAlo[row * 136 + c + 1]);
        split2h(v.z, sAhi[row * 136 + c + 2], sAlo[row * 136 + c + 2]);
        split2h(v.w, sAhi[row * 136 + c + 3], sAlo[row * 136 + c + 3]);
    }
    __syncthreads();

    int mrow = (warp & 3) * 16;
    int ncol = (warp >> 2) * 32;
    wmma::fragment<wmma::accumulator, 16, 16, 16, float> fc[2];
#pragma unroll
    for (int i = 0; i < 2; i++) wmma::fill_fragment(fc[i], 0.f);
#pragma unroll
    for (int ks = 0; ks < 8; ks++) {
        wmma::fragment<wmma::matrix_a, 16, 16, 16, __half, wmma::row_major> fah, fal;
        wmma::load_matrix_sync(fah, sAhi + mrow * 136 + ks * 16, 136);
        wmma::load_matrix_sync(fal, sAlo + mrow * 136 + ks * 16, 136);
#pragma unroll
        for (int ct = 0; ct < 2; ct++) {
            wmma::fragment<wmma::matrix_b, 16, 16, 16, __half, wmma::row_major> fbh, fbl;
            wmma::load_matrix_sync(fbh, sWhi + (ks * 16) * 72 + ncol + ct * 16, 72);
            wmma::load_matrix_sync(fbl, sWlo + (ks * 16) * 72 + ncol + ct * 16, 72);
            wmma::mma_sync(fc[ct], fah, fbh, fc[ct]);
            wmma::mma_sync(fc[ct], fal, fbh, fc[ct]);
            wmma::mma_sync(fc[ct], fah, fbl, fc[ct]);
        }
    }
    __syncthreads();
    float* stage = (float*)sAhi;  // 64 x 72
#pragma unroll
    for (int ct = 0; ct < 2; ct++)
        wmma::store_matrix_sync(stage + mrow * 72 + ncol + ct * 16, fc[ct], 72,
                                wmma::mem_row_major);
    __syncthreads();
    if (tid < 128) {
        int row = tid >> 1, o = tid & 1;
        int gr = row0 + row;
        if (gr < NN) {
            float s = b2[o];
            for (int k = 0; k < 64; k++) {
                float hv = stage[row * 72 + k] + b1[k];
                hv = hv > 0.f ? hv : 0.f;
                s += hv * w2[k * 2 + o];
            }
            out[(size_t)gr * 2 + o] = s;
        }
    }
}

// ---------------- host orchestration -----------------------------------------
extern "C" void kernel_launch(void* const* d_in, const int* in_sizes, int n_in,
                              void* d_out, int out_size) {
    const int* x = (const int*)d_in[0];
    const int* src = (const int*)d_in[1];
    const int* dst = (const int*)d_in[2];
    const float* snorm_n = (const float*)d_in[3];
    const float* embed = (const float*)d_in[5];
    const float* W[3] = {(const float*)d_in[6], (const float*)d_in[11], (const float*)d_in[16]};
    const float* al[3] = {(const float*)d_in[7], (const float*)d_in[12], (const float*)d_in[17]};
    const float* ar[3] = {(const float*)d_in[8], (const float*)d_in[13], (const float*)d_in[18]};
    const float* gamma[3] = {(const float*)d_in[9], (const float*)d_in[14], (const float*)d_in[19]};
    const float* beta[3] = {(const float*)d_in[10], (const float*)d_in[15], (const float*)d_in[20]};
    const float* cls1_w = (const float*)d_in[21];
    const float* cls1_b = (const float*)d_in[22];
    const float* cls2_w = (const float*)d_in[23];
    const float* cls2_b = (const float*)d_in[24];
    float* out = (float*)d_out;

    float *h0, *h1, *el, *er, *bnstat;
    __half* feath;
    int *deg, *rowptr, *cursor, *csr, *partial, *poff;
    cudaGetSymbolAddress((void**)&h0, g_h0);
    cudaGetSymbolAddress((void**)&h1, g_h1);
    cudaGetSymbolAddress((void**)&feath, g_feath);
    cudaGetSymbolAddress((void**)&el, g_el);
    cudaGetSymbolAddress((void**)&er, g_er);
    cudaGetSymbolAddress((void**)&bnstat, g_bnstat);
    cudaGetSymbolAddress((void**)&deg, g_deg);
    cudaGetSymbolAddress((void**)&rowptr, g_rowptr);
    cudaGetSymbolAddress((void**)&cursor, g_cursor);
    cudaGetSymbolAddress((void**)&csr, g_csr);
    cudaGetSymbolAddress((void**)&partial, g_partial);
    cudaGetSymbolAddress((void**)&poff, g_poff);

    // smem: W(2*128*136) + A(2*64*136) halves
    const int GEMM_SMEM = (2 * 128 * 136 + 2 * 64 * 136) * 2;  // 104448
    const int CLS_SMEM  = (2 * 128 * 72 + 2 * 64 * 136) * 2;   // 71680
    static bool attr_done = false;
    if (!attr_done) {
        cudaFuncSetAttribute(k_gemm<true>, cudaFuncAttributeMaxDynamicSharedMemorySize, GEMM_SMEM);
        cudaFuncSetAttribute(k_gemm<false>, cudaFuncAttributeMaxDynamicSharedMemorySize, GEMM_SMEM);
        cudaFuncSetAttribute(k_cls, cudaFuncAttributeMaxDynamicSharedMemorySize, CLS_SMEM);
        attr_done = true;
    }
    const int NSCAN = (NN + 255) / 256;  // 196
    const int GB = (NN + 63) / 64;       // 782

    cudaMemsetAsync(deg, 0, NN * sizeof(int), 0);
    cudaMemsetAsync(bnstat, 0, 3 * 256 * sizeof(float), 0);

    k_hist<<<(EE + 255) / 256, 256>>>(dst, deg);
    k_scan1<<<NSCAN, 256>>>(deg, partial);
    k_scan2<<<1, 256>>>(partial, poff, NSCAN);
    k_gemm<true><<<GB, 256, GEMM_SMEM>>>(nullptr, x, embed, W[0],
                                         nullptr, nullptr, nullptr, feath);
    k_scan3<<<NSCAN, 256>>>(deg, poff, rowptr, cursor);
    k_fill<<<(EE + 255) / 256, 256>>>(src, dst, cursor, csr);
    k_eler<<<NN / 2, 256>>>(feath, al[0], ar[0], el, er);
    k_agg<false, false><<<NN / 8, 256>>>(feath, nullptr, (const float4*)el,
                                         (const float4*)er, snorm_n, rowptr, csr,
                                         h0, &bnstat[0], nullptr, nullptr, nullptr);
    // layer 1
    k_gemm<false><<<GB, 256, GEMM_SMEM>>>(h0, nullptr, nullptr, W[1],
                                          &bnstat[0], gamma[0], beta[0], feath);
    k_eler<<<NN / 2, 256>>>(feath, al[1], ar[1], el, er);
    k_agg<true, true><<<NN / 8, 256>>>(feath, h0, (const float4*)el,
                                       (const float4*)er, snorm_n, rowptr, csr,
                                       h1, &bnstat[256], &bnstat[0], gamma[0], beta[0]);
    // layer 2
    k_gemm<false><<<GB, 256, GEMM_SMEM>>>(h1, nullptr, nullptr, W[2],
                                          &bnstat[256], gamma[1], beta[1], feath);
    k_eler<<<NN / 2, 256>>>(feath, al[2], ar[2], el, er);
    k_agg<true, true><<<NN / 8, 256>>>(feath, h1, (const float4*)el,
                                       (const float4*)er, snorm_n, rowptr, csr,
                                       h0, &bnstat[512], &bnstat[256], gamma[1], beta[1]);
    // classifier
    k_cls<<<GB, 256, CLS_SMEM>>>(h0, cls1_w, cls1_b, cls2_w, cls2_b,
                                 &bnstat[512], gamma[2], beta[2], out);
}

// round 5
// speedup vs baseline: 1.9110x; 1.1245x over previous
#include <cuda_runtime.h>
#include <cuda_fp16.h>
#include <mma.h>
using namespace nvcuda;

#define NN 50000
#define EE 850000
#define NTILES 782   // ceil(NN/64)
#define PGRID 304

// ---------------- scratch (device globals) ----------------------------------
__device__ float  g_h0[NN * 128];
__device__ float  g_h1[NN * 128];
__device__ __half g_feath[NN * 128];
__device__ float  g_el[NN * 4];
__device__ float  g_er[NN * 4];
__device__ int    g_deg[NN];
__device__ int    g_rowptr[NN + 1];
__device__ int    g_cursor[NN];
__device__ int    g_csr[EE];
__device__ int    g_partial[256];
__device__ int    g_poff[256];
__device__ float  g_bnstat[3 * 256];

__device__ __forceinline__ float eluf(float x) { return x > 0.f ? x : (__expf(x) - 1.f); }
__device__ __forceinline__ float lrelu(float x) { return x > 0.f ? x : 0.2f * x; }

__device__ __forceinline__ void split2h(float v, __half& hi, __half& lo) {
    hi = __float2half_rn(v);
    lo = __float2half_rn(v - __half2float(hi));
}

// ---------------- CSR build --------------------------------------------------
__global__ void k_hist(const int* __restrict__ dst, int* deg) {
    int i = blockIdx.x * blockDim.x + threadIdx.x;
    if (i < EE) atomicAdd(&deg[dst[i]], 1);
}

__device__ __forceinline__ int block_scan_excl(int v, int t) {
    __shared__ int ws[8];
    int lane = t & 31, w = t >> 5;
    int incl = v;
#pragma unroll
    for (int o = 1; o < 32; o <<= 1) {
        int u = __shfl_up_sync(0xffffffffu, incl, o);
        if (lane >= o) incl += u;
    }
    if (lane == 31) ws[w] = incl;
    __syncthreads();
    if (t == 0) {
        int run = 0;
#pragma unroll
        for (int i = 0; i < 8; i++) { int x = ws[i]; ws[i] = run; run += x; }
    }
    __syncthreads();
    return incl - v + ws[w];
}

__global__ void k_scan1(const int* __restrict__ deg, int* __restrict__ partial) {
    __shared__ int ws[8];
    int t = threadIdx.x, idx = blockIdx.x * 256 + t;
    int v = (idx < NN) ? deg[idx] : 0;
#pragma unroll
    for (int o = 16; o > 0; o >>= 1) v += __shfl_xor_sync(0xffffffffu, v, o);
    if ((t & 31) == 0) ws[t >> 5] = v;
    __syncthreads();
    if (t == 0) {
        int s = 0;
#pragma unroll
        for (int i = 0; i < 8; i++) s += ws[i];
        partial[blockIdx.x] = s;
    }
}

__global__ void k_scan2(const int* __restrict__ partial, int* __restrict__ poff, int nblk) {
    int t = threadIdx.x;
    int v = (t < nblk) ? partial[t] : 0;
    int excl = block_scan_excl(v, t);
    if (t < nblk) poff[t] = excl;
}

__global__ void k_scan3(const int* __restrict__ deg, const int* __restrict__ poff,
                        int* __restrict__ rowptr, int* __restrict__ cursor) {
    int t = threadIdx.x, idx = blockIdx.x * 256 + t;
    int v = (idx < NN) ? deg[idx] : 0;
    int excl = block_scan_excl(v, t);
    int res = poff[blockIdx.x] + excl;
    if (idx <= NN) rowptr[idx] = res;
    if (idx < NN) cursor[idx] = res;
}

__global__ void k_fill(const int* __restrict__ src, const int* __restrict__ dst,
                       int* cursor, int* __restrict__ csr) {
    int i = blockIdx.x * blockDim.x + threadIdx.x;
    if (i < EE) {
        int d = dst[i];
        int pos = atomicAdd(&cursor[d], 1);
        csr[pos] = src[i];
    }
}

// ---------------- persistent split-FP16 HMMA GEMM + fused el/er --------------
// W resident in smem per block; grid-stride over 64-row tiles.
// L0: A = embed[x[row]]; else A = elu(BN_prev(hin)).
template <bool L0>
__global__ void k_gemm(const float* __restrict__ A, const int* __restrict__ xidx,
                       const float* __restrict__ embed, const float* __restrict__ W,
                       const float* __restrict__ stat, const float* __restrict__ gamma,
                       const float* __restrict__ beta, const float* __restrict__ alv,
                       const float* __restrict__ arv, __half* __restrict__ feat,
                       float* __restrict__ el, float* __restrict__ er) {
    extern __shared__ __half smh[];
    __half* sWhi = smh;                    // 128 x 136
    __half* sWlo = sWhi + 128 * 136;       // 128 x 136
    __half* sAhi = sWlo + 128 * 136;       // 64 x 136
    __half* sAlo = sAhi + 64 * 136;        // 64 x 136
    __shared__ float sc[128], shf[128];
    __shared__ float s_al[128], s_ar[128];
    int tid = threadIdx.x, warp = tid >> 5;

    if (!L0) {
        if (tid < 128) {
            float mu = stat[tid] * (1.f / NN);
            float var = stat[128 + tid] * (1.f / NN) - mu * mu;
            float r = rsqrtf(var + 1e-5f);
            sc[tid] = gamma[tid] * r;
            shf[tid] = beta[tid] - mu * gamma[tid] * r;
        }
    }
    if (tid < 128) { s_al[tid] = alv[tid]; s_ar[tid] = arv[tid]; }

    // load + split W once per block
    for (int p = tid; p < 4096; p += 256) {
        int r = p >> 5, c = (p & 31) * 4;
        float4 v = *(const float4*)&W[(size_t)r * 128 + c];
        split2h(v.x, sWhi[r * 136 + c], sWlo[r * 136 + c]);
        split2h(v.y, sWhi[r * 136 + c + 1], sWlo[r * 136 + c + 1]);
        split2h(v.z, sWhi[r * 136 + c + 2], sWlo[r * 136 + c + 2]);
        split2h(v.w, sWhi[r * 136 + c + 3], sWlo[r * 136 + c + 3]);
    }

    int mrow = (warp & 3) * 16;
    int ncol = (warp >> 2) * 64;

    for (int tile = blockIdx.x; tile < NTILES; tile += gridDim.x) {
        int row0 = tile * 64;
        __syncthreads();   // W ready (1st iter) / stage consumed (later iters)
        for (int p = tid; p < 2048; p += 256) {
            int row = p >> 5, c = (p & 31) * 4;
            int gr = row0 + row;
            float4 v = make_float4(0.f, 0.f, 0.f, 0.f);
            if (gr < NN) {
                if (L0) v = *(const float4*)&embed[(size_t)xidx[gr] * 128 + c];
                else {
                    v = *(const float4*)&A[(size_t)gr * 128 + c];
                    v.x = eluf(v.x * sc[c] + shf[c]);
                    v.y = eluf(v.y * sc[c + 1] + shf[c + 1]);
                    v.z = eluf(v.z * sc[c + 2] + shf[c + 2]);
                    v.w = eluf(v.w * sc[c + 3] + shf[c + 3]);
                }
            }
            split2h(v.x, sAhi[row * 136 + c], sAlo[row * 136 + c]);
            split2h(v.y, sAhi[row * 136 + c + 1], sAlo[row * 136 + c + 1]);
            split2h(v.z, sAhi[row * 136 + c + 2], sAlo[row * 136 + c + 2]);
            split2h(v.w, sAhi[row * 136 + c + 3], sAlo[row * 136 + c + 3]);
        }
        __syncthreads();

        wmma::fragment<wmma::accumulator, 16, 16, 16, float> fc[4];
#pragma unroll
        for (int i = 0; i < 4; i++) wmma::fill_fragment(fc[i], 0.f);
#pragma unroll
        for (int ks = 0; ks < 8; ks++) {
            wmma::fragment<wmma::matrix_a, 16, 16, 16, __half, wmma::row_major> fah, fal;
            wmma::load_matrix_sync(fah, sAhi + mrow * 136 + ks * 16, 136);
            wmma::load_matrix_sync(fal, sAlo + mrow * 136 + ks * 16, 136);
#pragma unroll
            for (int ct = 0; ct < 4; ct++) {
                wmma::fragment<wmma::matrix_b, 16, 16, 16, __half, wmma::row_major> fbh, fbl;
                wmma::load_matrix_sync(fbh, sWhi + (ks * 16) * 136 + ncol + ct * 16, 136);
                wmma::load_matrix_sync(fbl, sWlo + (ks * 16) * 136 + ncol + ct * 16, 136);
                wmma::mma_sync(fc[ct], fah, fbh, fc[ct]);
                wmma::mma_sync(fc[ct], fal, fbh, fc[ct]);
                wmma::mma_sync(fc[ct], fah, fbl, fc[ct]);
            }
        }
        __syncthreads();   // A reads done -> safe to overwrite with stage
        float* stage = (float*)sAhi;   // 64 x 136 floats
#pragma unroll
        for (int ct = 0; ct < 4; ct++)
            wmma::store_matrix_sync(stage + mrow * 136 + ncol + ct * 16, fc[ct], 136,
                                    wmma::mem_row_major);
        __syncthreads();

        // feat fp16 store
        for (int p = tid; p < 1024; p += 256) {
            int row = p >> 4, c8 = (p & 15) * 8;
            int gr = row0 + row;
            if (gr < NN) {
                const float* s = stage + row * 136 + c8;
                __half2 h0 = __floats2half2_rn(s[0], s[1]);
                __half2 h1 = __floats2half2_rn(s[2], s[3]);
                __half2 h2 = __floats2half2_rn(s[4], s[5]);
                __half2 h3 = __floats2half2_rn(s[6], s[7]);
                uint4 pack;
                pack.x = *(unsigned*)&h0; pack.y = *(unsigned*)&h1;
                pack.z = *(unsigned*)&h2; pack.w = *(unsigned*)&h3;
                *(uint4*)(feat + (size_t)gr * 128 + c8) = pack;
            }
        }
        // fused el/er: 64 rows x 8 outputs (4 el heads, 4 er heads)
        for (int p = tid; p < 512; p += 256) {
            int row = p >> 3, c = p & 7;
            int h = c & 3;
            int gr = row0 + row;
            const float* srow = stage + row * 136 + h * 32;
            const float* av = (c < 4) ? s_al + h * 32 : s_ar + h * 32;
            float s = 0.f;
#pragma unroll
            for (int dd = 0; dd < 32; dd++) {
                int d = (dd + c * 4) & 31;   // stagger to avoid bank conflicts
                s += srow[d] * av[d];
            }
            if (gr < NN) {
                if (c < 4) el[gr * 4 + h] = s;
                else       er[gr * 4 + h] = s;
            }
        }
    }
}

// ---------------- fused softmax + aggregation + BN stats ---------------------
template <bool RES, bool ACT>
__global__ void k_agg(const __half* __restrict__ feat, const float* __restrict__ hin,
                      const float4* __restrict__ el4, const float4* __restrict__ er4,
                      const float* __restrict__ snorm, const int* __restrict__ rowptr,
                      const int* __restrict__ csr, float* __restrict__ out,
                      float* __restrict__ bnstat, const float* __restrict__ pstat,
                      const float* __restrict__ pgamma, const float* __restrict__ pbeta) {
    __shared__ int   s_sj[8][32];
    __shared__ float s_a[8][32][4];
    __shared__ float bs[1024];
    __shared__ float bq[1024];
    __shared__ float psc[128], psh[128];
    int warp = threadIdx.x >> 5;
    int lane = threadIdx.x & 31;
    int node = blockIdx.x * 8 + warp;
    if (RES) {
        int t = threadIdx.x;
        if (t < 128) {
            float mu = pstat[t] * (1.f / NN);
            float var = pstat[128 + t] * (1.f / NN) - mu * mu;
            float r = rsqrtf(var + 1e-5f);
            psc[t] = pgamma[t] * r;
            psh[t] = pbeta[t] - mu * pgamma[t] * r;
        }
        __syncthreads();
    }
    int start = rowptr[node], end = rowptr[node + 1];
    int deg = end - start;
    float4 er = er4[node];
    int hl = lane >> 3;
    int c0 = lane * 4;

    float4 acc = make_float4(0.f, 0.f, 0.f, 0.f);
    if (RES) {
        float4 h = *(const float4*)&hin[(size_t)node * 128 + c0];
        acc.x = eluf(h.x * psc[c0] + psh[c0]);
        acc.y = eluf(h.y * psc[c0 + 1] + psh[c0 + 1]);
        acc.z = eluf(h.z * psc[c0 + 2] + psh[c0 + 2]);
        acc.w = eluf(h.w * psc[c0 + 3] + psh[c0 + 3]);
    }

    if (deg <= 32) {
        bool on = lane < deg;
        int s = on ? csr[start + lane] : 0;
        float4 v = make_float4(-3e38f, -3e38f, -3e38f, -3e38f);
        if (on) {
            float4 e = el4[s];
            v.x = lrelu(e.x + er.x); v.y = lrelu(e.y + er.y);
            v.z = lrelu(e.z + er.z); v.w = lrelu(e.w + er.w);
        }
        float4 mx = v;
#pragma unroll
        for (int o = 16; o > 0; o >>= 1) {
            mx.x = fmaxf(mx.x, __shfl_xor_sync(0xffffffffu, mx.x, o));
            mx.y = fmaxf(mx.y, __shfl_xor_sync(0xffffffffu, mx.y, o));
            mx.z = fmaxf(mx.z, __shfl_xor_sync(0xffffffffu, mx.z, o));
            mx.w = fmaxf(mx.w, __shfl_xor_sync(0xffffffffu, mx.w, o));
        }
        float4 ex = make_float4(0.f, 0.f, 0.f, 0.f);
        if (on) {
            ex.x = __expf(v.x - mx.x); ex.y = __expf(v.y - mx.y);
            ex.z = __expf(v.z - mx.z); ex.w = __expf(v.w - mx.w);
        }
        float4 sm4 = ex;
#pragma unroll
        for (int o = 16; o > 0; o >>= 1) {
            sm4.x += __shfl_xor_sync(0xffffffffu, sm4.x, o);
            sm4.y += __shfl_xor_sync(0xffffffffu, sm4.y, o);
            sm4.z += __shfl_xor_sync(0xffffffffu, sm4.z, o);
            sm4.w += __shfl_xor_sync(0xffffffffu, sm4.w, o);
        }
        s_sj[warp][lane] = s;
        float4 aex = make_float4(ex.x / sm4.x, ex.y / sm4.y, ex.z / sm4.z, ex.w / sm4.w);
        *(float4*)&s_a[warp][lane][0] = aex;
        __syncwarp();
#pragma unroll 2
        for (int j = 0; j < deg; j++) {
            int sj = s_sj[warp][j];
            float a = s_a[warp][j][hl];
            uint2 raw = *(const uint2*)(feat + (size_t)sj * 128 + c0);
            float2 f01 = __half22float2(*(__half2*)&raw.x);
            float2 f23 = __half22float2(*(__half2*)&raw.y);
            acc.x += f01.x * a; acc.y += f01.y * a;
            acc.z += f23.x * a; acc.w += f23.y * a;
        }
    } else {
        float mx0 = -3e38f, mx1 = -3e38f, mx2 = -3e38f, mx3 = -3e38f;
        for (int k = start + lane; k < end; k += 32) {
            int s = csr[k];
            float4 e = el4[s];
            mx0 = fmaxf(mx0, lrelu(e.x + er.x)); mx1 = fmaxf(mx1, lrelu(e.y + er.y));
            mx2 = fmaxf(mx2, lrelu(e.z + er.z)); mx3 = fmaxf(mx3, lrelu(e.w + er.w));
        }
#pragma unroll
        for (int o = 16; o > 0; o >>= 1) {
            mx0 = fmaxf(mx0, __shfl_xor_sync(0xffffffffu, mx0, o));
            mx1 = fmaxf(mx1, __shfl_xor_sync(0xffffffffu, mx1, o));
            mx2 = fmaxf(mx2, __shfl_xor_sync(0xffffffffu, mx2, o));
            mx3 = fmaxf(mx3, __shfl_xor_sync(0xffffffffu, mx3, o));
        }
        float s0 = 0.f, s1 = 0.f, s2 = 0.f, s3 = 0.f;
        for (int k = start + lane; k < end; k += 32) {
            int s = csr[k];
            float4 e = el4[s];
            s0 += __expf(lrelu(e.x + er.x) - mx0);
            s1 += __expf(lrelu(e.y + er.y) - mx1);
            s2 += __expf(lrelu(e.z + er.z) - mx2);
            s3 += __expf(lrelu(e.w + er.w) - mx3);
        }
#pragma unroll
        for (int o = 16; o > 0; o >>= 1) {
            s0 += __shfl_xor_sync(0xffffffffu, s0, o);
            s1 += __shfl_xor_sync(0xffffffffu, s1, o);
            s2 += __shfl_xor_sync(0xffffffffu, s2, o);
            s3 += __shfl_xor_sync(0xffffffffu, s3, o);
        }
        float mxh = hl == 0 ? mx0 : hl == 1 ? mx1 : hl == 2 ? mx2 : mx3;
        float invh = 1.f / (hl == 0 ? s0 : hl == 1 ? s1 : hl == 2 ? s2 : s3);
        float erh = hl == 0 ? er.x : hl == 1 ? er.y : hl == 2 ? er.z : er.w;
#pragma unroll 2
        for (int k = start; k < end; k++) {
            int s = csr[k];
            float4 e = el4[s];
            float ev = hl == 0 ? e.x : hl == 1 ? e.y : hl == 2 ? e.z : e.w;
            float a = __expf(lrelu(ev + erh) - mxh) * invh;
            uint2 raw = *(const uint2*)(feat + (size_t)s * 128 + c0);
            float2 f01 = __half22float2(*(__half2*)&raw.x);
            float2 f23 = __half22float2(*(__half2*)&raw.y);
            acc.x += f01.x * a; acc.y += f01.y * a;
            acc.z += f23.x * a; acc.w += f23.y * a;
        }
    }
    if (ACT) {
        acc.x = eluf(acc.x); acc.y = eluf(acc.y);
        acc.z = eluf(acc.z); acc.w = eluf(acc.w);
    }
    float sn = snorm[node];
    acc.x *= sn; acc.y *= sn; acc.z *= sn; acc.w *= sn;
    *(float4*)&out[(size_t)node * 128 + c0] = acc;

    ((float4*)bs)[warp * 32 + lane] = acc;
    ((float4*)bq)[warp * 32 + lane] =
        make_float4(acc.x * acc.x, acc.y * acc.y, acc.z * acc.z, acc.w * acc.w);
    __syncthreads();
    int t = threadIdx.x;
    if (t < 128) {
        float s = 0.f, q = 0.f;
#pragma unroll
        for (int w = 0; w < 8; w++) { s += bs[w * 128 + t]; q += bq[w * 128 + t]; }
        atomicAdd(&bnstat[t], s);
        atomicAdd(&bnstat[128 + t], q);
    }
}

// ---------------- classifier: split-fp16 HMMA 128->64, then 64->2 ------------
__global__ void k_cls(const float* __restrict__ H, const float* __restrict__ w1,
                      const float* __restrict__ b1, const float* __restrict__ w2,
                      const float* __restrict__ b2, const float* __restrict__ stat,
                      const float* __restrict__ gamma, const float* __restrict__ beta,
                      float* __restrict__ out) {
    extern __shared__ __half smh[];
    __half* sWhi = smh;                  // 128 x 72
    __half* sWlo = sWhi + 128 * 72;      // 128 x 72
    __half* sAhi = sWlo + 128 * 72;      // 64 x 136
    __half* sAlo = sAhi + 64 * 136;      // 64 x 136
    __shared__ float sc[128], shf[128];
    int tid = threadIdx.x, warp = tid >> 5;
    int row0 = blockIdx.x * 64;
    if (tid < 128) {
        float mu = stat[tid] * (1.f / NN);
        float var = stat[128 + tid] * (1.f / NN) - mu * mu;
        float r = rsqrtf(var + 1e-5f);
        sc[tid] = gamma[tid] * r;
        shf[tid] = beta[tid] - mu * gamma[tid] * r;
    }
    __syncthreads();

    for (int p = tid; p < 2048; p += 256) {
        int r = p >> 4, c = (p & 15) * 4;
        float4 v = *(const float4*)&w1[(size_t)r * 64 + c];
        split2h(v.x, sWhi[r * 72 + c], sWlo[r * 72 + c]);
        split2h(v.y, sWhi[r * 72 + c + 1], sWlo[r * 72 + c + 1]);
        split2h(v.z, sWhi[r * 72 + c + 2], sWlo[r * 72 + c + 2]);
        split2h(v.w, sWhi[r * 72 + c + 3], sWlo[r * 72 + c + 3]);
    }
    for (int p = tid; p < 2048; p += 256) {
        int row = p >> 5, c = (p & 31) * 4;
        int gr = row0 + row;
        float4 v = make_float4(0.f, 0.f, 0.f, 0.f);
        if (gr < NN) {
            v = *(const float4*)&H[(size_t)gr * 128 + c];
            v.x = eluf(v.x * sc[c] + shf[c]);
            v.y = eluf(v.y * sc[c + 1] + shf[c + 1]);
            v.z = eluf(v.z * sc[c + 2] + shf[c + 2]);
            v.w = eluf(v.w * sc[c + 3] + shf[c + 3]);
        }
        split2h(v.x, sAhi[row * 136 + c], sAlo[row * 136 + c]);
        split2h(v.y, sAhi[row * 136 + c + 1], sAlo[row * 136 + c + 1]);
        split2h(v.z, sAhi[row * 136 + c + 2], sAlo[row * 136 + c + 2]);
        split2h(v.w, sAhi[row * 136 + c + 3], sAlo[row * 136 + c + 3]);
    }
    __syncthreads();

    int mrow = (warp & 3) * 16;
    int ncol = (warp >> 2) * 32;
    wmma::fragment<wmma::accumulator, 16, 16, 16, float> fc[2];
#pragma unroll
    for (int i = 0; i < 2; i++) wmma::fill_fragment(fc[i], 0.f);
#pragma unroll
    for (int ks = 0; ks < 8; ks++) {
        wmma::fragment<wmma::matrix_a, 16, 16, 16, __half, wmma::row_major> fah, fal;
        wmma::load_matrix_sync(fah, sAhi + mrow * 136 + ks * 16, 136);
        wmma::load_matrix_sync(fal, sAlo + mrow * 136 + ks * 16, 136);
#pragma unroll
        for (int ct = 0; ct < 2; ct++) {
            wmma::fragment<wmma::matrix_b, 16, 16, 16, __half, wmma::row_major> fbh, fbl;
            wmma::load_matrix_sync(fbh, sWhi + (ks * 16) * 72 + ncol + ct * 16, 72);
            wmma::load_matrix_sync(fbl, sWlo + (ks * 16) * 72 + ncol + ct * 16, 72);
            wmma::mma_sync(fc[ct], fah, fbh, fc[ct]);
            wmma::mma_sync(fc[ct], fal, fbh, fc[ct]);
            wmma::mma_sync(fc[ct], fah, fbl, fc[ct]);
        }
    }
    __syncthreads();
    float* stage = (float*)sAhi;  // 64 x 72
#pragma unroll
    for (int ct = 0; ct < 2; ct++)
        wmma::store_matrix_sync(stage + mrow * 72 + ncol + ct * 16, fc[ct], 72,
                                wmma::mem_row_major);
    __syncthreads();
    if (tid < 128) {
        int row = tid >> 1, o = tid & 1;
        int gr = row0 + row;
        if (gr < NN) {
            float s = b2[o];
            for (int k = 0; k < 64; k++) {
                float hv = stage[row * 72 + k] + b1[k];
                hv = hv > 0.f ? hv : 0.f;
                s += hv * w2[k * 2 + o];
            }
            out[(size_t)gr * 2 + o] = s;
        }
    }
}

// ---------------- host orchestration -----------------------------------------
extern "C" void kernel_launch(void* const* d_in, const int* in_sizes, int n_in,
                              void* d_out, int out_size) {
    const int* x = (const int*)d_in[0];
    const int* src = (const int*)d_in[1];
    const int* dst = (const int*)d_in[2];
    const float* snorm_n = (const float*)d_in[3];
    const float* embed = (const float*)d_in[5];
    const float* W[3] = {(const float*)d_in[6], (const float*)d_in[11], (const float*)d_in[16]};
    const float* al[3] = {(const float*)d_in[7], (const float*)d_in[12], (const float*)d_in[17]};
    const float* ar[3] = {(const float*)d_in[8], (const float*)d_in[13], (const float*)d_in[18]};
    const float* gamma[3] = {(const float*)d_in[9], (const float*)d_in[14], (const float*)d_in[19]};
    const float* beta[3] = {(const float*)d_in[10], (const float*)d_in[15], (const float*)d_in[20]};
    const float* cls1_w = (const float*)d_in[21];
    const float* cls1_b = (const float*)d_in[22];
    const float* cls2_w = (const float*)d_in[23];
    const float* cls2_b = (const float*)d_in[24];
    float* out = (float*)d_out;

    float *h0, *h1, *el, *er, *bnstat;
    __half* feath;
    int *deg, *rowptr, *cursor, *csr, *partial, *poff;
    cudaGetSymbolAddress((void**)&h0, g_h0);
    cudaGetSymbolAddress((void**)&h1, g_h1);
    cudaGetSymbolAddress((void**)&feath, g_feath);
    cudaGetSymbolAddress((void**)&el, g_el);
    cudaGetSymbolAddress((void**)&er, g_er);
    cudaGetSymbolAddress((void**)&bnstat, g_bnstat);
    cudaGetSymbolAddress((void**)&deg, g_deg);
    cudaGetSymbolAddress((void**)&rowptr, g_rowptr);
    cudaGetSymbolAddress((void**)&cursor, g_cursor);
    cudaGetSymbolAddress((void**)&csr, g_csr);
    cudaGetSymbolAddress((void**)&partial, g_partial);
    cudaGetSymbolAddress((void**)&poff, g_poff);

    const int GEMM_SMEM = (2 * 128 * 136 + 2 * 64 * 136) * 2;  // 104448
    const int CLS_SMEM  = (2 * 128 * 72 + 2 * 64 * 136) * 2;   // 71680
    static bool attr_done = false;
    if (!attr_done) {
        cudaFuncSetAttribute(k_gemm<true>, cudaFuncAttributeMaxDynamicSharedMemorySize, GEMM_SMEM);
        cudaFuncSetAttribute(k_gemm<false>, cudaFuncAttributeMaxDynamicSharedMemorySize, GEMM_SMEM);
        cudaFuncSetAttribute(k_cls, cudaFuncAttributeMaxDynamicSharedMemorySize, CLS_SMEM);
        attr_done = true;
    }
    const int NSCAN = (NN + 255) / 256;  // 196

    cudaMemsetAsync(deg, 0, NN * sizeof(int), 0);
    cudaMemsetAsync(bnstat, 0, 3 * 256 * sizeof(float), 0);

    k_hist<<<(EE + 255) / 256, 256>>>(dst, deg);
    k_scan1<<<NSCAN, 256>>>(deg, partial);
    k_scan2<<<1, 256>>>(partial, poff, NSCAN);
    k_gemm<true><<<PGRID, 256, GEMM_SMEM>>>(nullptr, x, embed, W[0],
                                            nullptr, nullptr, nullptr,
                                            al[0], ar[0], feath, el, er);
    k_scan3<<<NSCAN, 256>>>(deg, poff, rowptr, cursor);
    k_fill<<<(EE + 255) / 256, 256>>>(src, dst, cursor, csr);
    k_agg<false, false><<<NN / 8, 256>>>(feath, nullptr, (const float4*)el,
                                         (const float4*)er, snorm_n, rowptr, csr,
                                         h0, &bnstat[0], nullptr, nullptr, nullptr);
    // layer 1
    k_gemm<false><<<PGRID, 256, GEMM_SMEM>>>(h0, nullptr, nullptr, W[1],
                                             &bnstat[0], gamma[0], beta[0],
                                             al[1], ar[1], feath, el, er);
    k_agg<true, true><<<NN / 8, 256>>>(feath, h0, (const float4*)el,
                                       (const float4*)er, snorm_n, rowptr, csr,
                                       h1, &bnstat[256], &bnstat[0], gamma[0], beta[0]);
    // layer 2
    k_gemm<false><<<PGRID, 256, GEMM_SMEM>>>(h1, nullptr, nullptr, W[2],
                                             &bnstat[256], gamma[1], beta[1],
                                             al[2], ar[2], feath, el, er);
    k_agg<true, true><<<NN / 8, 256>>>(feath, h1, (const float4*)el,
                                       (const float4*)er, snorm_n, rowptr, csr,
                                       h0, &bnstat[512], &bnstat[256], gamma[1], beta[1]);
    // classifier
    k_cls<<<(NN + 63) / 64, 256, CLS_SMEM>>>(h0, cls1_w, cls1_b, cls2_w, cls2_b,
                                             &bnstat[512], gamma[2], beta[2], out);
}

// round 6
// speedup vs baseline: 1.9897x; 1.0412x over previous
#include <cuda_runtime.h>
#include <cuda_fp16.h>
#include <mma.h>
using namespace nvcuda;

#define NN 50000
#define EE 850000
#define NTILES 782   // ceil(NN/64)
#define PGRID 444

// ---------------- scratch (device globals) ----------------------------------
__device__ float  g_h0[NN * 128];
__device__ float  g_h1[NN * 128];
__device__ __half g_feath[NN * 128];
__device__ float  g_el[NN * 4];
__device__ float  g_er[NN * 4];
__device__ int    g_deg[NN];
__device__ int    g_rowptr[NN + 1];
__device__ int    g_cursor[NN];
__device__ int    g_csr[EE];
__device__ int    g_partial[256];
__device__ int    g_poff[256];
__device__ float  g_bnstat[3 * 256];

__device__ __forceinline__ float eluf(float x) { return x > 0.f ? x : (__expf(x) - 1.f); }
__device__ __forceinline__ float lrelu(float x) { return x > 0.f ? x : 0.2f * x; }

__device__ __forceinline__ void split2h(float v, __half& hi, __half& lo) {
    hi = __float2half_rn(v);
    lo = __float2half_rn(v - __half2float(hi));
}

// ---------------- CSR build --------------------------------------------------
__global__ void k_hist(const int* __restrict__ dst, int* deg) {
    int i = blockIdx.x * blockDim.x + threadIdx.x;
    if (i < EE) atomicAdd(&deg[dst[i]], 1);
}

__device__ __forceinline__ int block_scan_excl(int v, int t) {
    __shared__ int ws[8];
    int lane = t & 31, w = t >> 5;
    int incl = v;
#pragma unroll
    for (int o = 1; o < 32; o <<= 1) {
        int u = __shfl_up_sync(0xffffffffu, incl, o);
        if (lane >= o) incl += u;
    }
    if (lane == 31) ws[w] = incl;
    __syncthreads();
    if (t == 0) {
        int run = 0;
#pragma unroll
        for (int i = 0; i < 8; i++) { int x = ws[i]; ws[i] = run; run += x; }
    }
    __syncthreads();
    return incl - v + ws[w];
}

__global__ void k_scan1(const int* __restrict__ deg, int* __restrict__ partial) {
    __shared__ int ws[8];
    int t = threadIdx.x, idx = blockIdx.x * 256 + t;
    int v = (idx < NN) ? deg[idx] : 0;
#pragma unroll
    for (int o = 16; o > 0; o >>= 1) v += __shfl_xor_sync(0xffffffffu, v, o);
    if ((t & 31) == 0) ws[t >> 5] = v;
    __syncthreads();
    if (t == 0) {
        int s = 0;
#pragma unroll
        for (int i = 0; i < 8; i++) s += ws[i];
        partial[blockIdx.x] = s;
    }
}

__global__ void k_scan2(const int* __restrict__ partial, int* __restrict__ poff, int nblk) {
    int t = threadIdx.x;
    int v = (t < nblk) ? partial[t] : 0;
    int excl = block_scan_excl(v, t);
    if (t < nblk) poff[t] = excl;
}

__global__ void k_scan3(const int* __restrict__ deg, const int* __restrict__ poff,
                        int* __restrict__ rowptr, int* __restrict__ cursor) {
    int t = threadIdx.x, idx = blockIdx.x * 256 + t;
    int v = (idx < NN) ? deg[idx] : 0;
    int excl = block_scan_excl(v, t);
    int res = poff[blockIdx.x] + excl;
    if (idx <= NN) rowptr[idx] = res;
    if (idx < NN) cursor[idx] = res;
}

__global__ void k_fill(const int* __restrict__ src, const int* __restrict__ dst,
                       int* cursor, int* __restrict__ csr) {
    int i = blockIdx.x * blockDim.x + threadIdx.x;
    if (i < EE) {
        int d = dst[i];
        int pos = atomicAdd(&cursor[d], 1);
        csr[pos] = src[i];
    }
}

// ---------------- persistent HMMA GEMM (A split, W fp16) + fused el/er -------
template <bool L0>
__global__ void k_gemm(const float* __restrict__ A, const int* __restrict__ xidx,
                       const float* __restrict__ embed, const float* __restrict__ W,
                       const float* __restrict__ stat, const float* __restrict__ gamma,
                       const float* __restrict__ beta, const float* __restrict__ alv,
                       const float* __restrict__ arv, __half* __restrict__ feat,
                       float* __restrict__ el, float* __restrict__ er) {
    extern __shared__ __half smh[];
    __half* sW   = smh;                    // 128 x 136
    __half* sAhi = sW + 128 * 136;         // 64 x 136
    __half* sAlo = sAhi + 64 * 136;        // 64 x 136
    __shared__ float sc[128], shf[128];
    __shared__ float s_al[128], s_ar[128];
    int tid = threadIdx.x, warp = tid >> 5;

    if (!L0) {
        if (tid < 128) {
            float mu = stat[tid] * (1.f / NN);
            float var = stat[128 + tid] * (1.f / NN) - mu * mu;
            float r = rsqrtf(var + 1e-5f);
            sc[tid] = gamma[tid] * r;
            shf[tid] = beta[tid] - mu * gamma[tid] * r;
        }
    }
    if (tid < 128) { s_al[tid] = alv[tid]; s_ar[tid] = arv[tid]; }

    // load W (fp16 round) once per block
    for (int p = tid; p < 4096; p += 256) {
        int r = p >> 5, c = (p & 31) * 4;
        float4 v = *(const float4*)&W[(size_t)r * 128 + c];
        sW[r * 136 + c]     = __float2half_rn(v.x);
        sW[r * 136 + c + 1] = __float2half_rn(v.y);
        sW[r * 136 + c + 2] = __float2half_rn(v.z);
        sW[r * 136 + c + 3] = __float2half_rn(v.w);
    }

    int mrow = (warp & 3) * 16;
    int ncol = (warp >> 2) * 64;

    for (int tile = blockIdx.x; tile < NTILES; tile += gridDim.x) {
        int row0 = tile * 64;
        __syncthreads();   // W ready / stage consumed
        for (int p = tid; p < 2048; p += 256) {
            int row = p >> 5, c = (p & 31) * 4;
            int gr = row0 + row;
            float4 v = make_float4(0.f, 0.f, 0.f, 0.f);
            if (gr < NN) {
                if (L0) v = *(const float4*)&embed[(size_t)xidx[gr] * 128 + c];
                else {
                    v = *(const float4*)&A[(size_t)gr * 128 + c];
                    v.x = eluf(v.x * sc[c] + shf[c]);
                    v.y = eluf(v.y * sc[c + 1] + shf[c + 1]);
                    v.z = eluf(v.z * sc[c + 2] + shf[c + 2]);
                    v.w = eluf(v.w * sc[c + 3] + shf[c + 3]);
                }
            }
            split2h(v.x, sAhi[row * 136 + c], sAlo[row * 136 + c]);
            split2h(v.y, sAhi[row * 136 + c + 1], sAlo[row * 136 + c + 1]);
            split2h(v.z, sAhi[row * 136 + c + 2], sAlo[row * 136 + c + 2]);
            split2h(v.w, sAhi[row * 136 + c + 3], sAlo[row * 136 + c + 3]);
        }
        __syncthreads();

        wmma::fragment<wmma::accumulator, 16, 16, 16, float> fc[4];
#pragma unroll
        for (int i = 0; i < 4; i++) wmma::fill_fragment(fc[i], 0.f);
#pragma unroll
        for (int ks = 0; ks < 8; ks++) {
            wmma::fragment<wmma::matrix_a, 16, 16, 16, __half, wmma::row_major> fah, fal;
            wmma::load_matrix_sync(fah, sAhi + mrow * 136 + ks * 16, 136);
            wmma::load_matrix_sync(fal, sAlo + mrow * 136 + ks * 16, 136);
#pragma unroll
            for (int ct = 0; ct < 4; ct++) {
                wmma::fragment<wmma::matrix_b, 16, 16, 16, __half, wmma::row_major> fb;
                wmma::load_matrix_sync(fb, sW + (ks * 16) * 136 + ncol + ct * 16, 136);
                wmma::mma_sync(fc[ct], fah, fb, fc[ct]);
                wmma::mma_sync(fc[ct], fal, fb, fc[ct]);
            }
        }
        __syncthreads();   // A reads done
        float* stage = (float*)sAhi;   // 64 x 136 floats (covers both A bufs)
#pragma unroll
        for (int ct = 0; ct < 4; ct++)
            wmma::store_matrix_sync(stage + mrow * 136 + ncol + ct * 16, fc[ct], 136,
                                    wmma::mem_row_major);
        __syncthreads();

        for (int p = tid; p < 1024; p += 256) {
            int row = p >> 4, c8 = (p & 15) * 8;
            int gr = row0 + row;
            if (gr < NN) {
                const float* s = stage + row * 136 + c8;
                __half2 h0 = __floats2half2_rn(s[0], s[1]);
                __half2 h1 = __floats2half2_rn(s[2], s[3]);
                __half2 h2 = __floats2half2_rn(s[4], s[5]);
                __half2 h3 = __floats2half2_rn(s[6], s[7]);
                uint4 pack;
                pack.x = *(unsigned*)&h0; pack.y = *(unsigned*)&h1;
                pack.z = *(unsigned*)&h2; pack.w = *(unsigned*)&h3;
                *(uint4*)(feat + (size_t)gr * 128 + c8) = pack;
            }
        }
        for (int p = tid; p < 512; p += 256) {
            int row = p >> 3, c = p & 7;
            int h = c & 3;
            int gr = row0 + row;
            const float* srow = stage + row * 136 + h * 32;
            const float* av = (c < 4) ? s_al + h * 32 : s_ar + h * 32;
            float s = 0.f;
#pragma unroll
            for (int dd = 0; dd < 32; dd++) {
                int d = (dd + c * 4) & 31;
                s += srow[d] * av[d];
            }
            if (gr < NN) {
                if (c < 4) el[gr * 4 + h] = s;
                else       er[gr * 4 + h] = s;
            }
        }
    }
}

// ---------------- fused softmax + aggregation + BN stats ---------------------
template <bool RES, bool ACT>
__global__ void k_agg(const __half* __restrict__ feat, const float* __restrict__ hin,
                      const float4* __restrict__ el4, const float4* __restrict__ er4,
                      const float* __restrict__ snorm, const int* __restrict__ rowptr,
                      const int* __restrict__ csr, float* __restrict__ out,
                      float* __restrict__ bnstat, const float* __restrict__ pstat,
                      const float* __restrict__ pgamma, const float* __restrict__ pbeta) {
    __shared__ int   s_sj[8][32];
    __shared__ float s_a[8][32][4];
    __shared__ float bs[1024];
    __shared__ float bq[1024];
    __shared__ float psc[128], psh[128];
    int warp = threadIdx.x >> 5;
    int lane = threadIdx.x & 31;
    int node = blockIdx.x * 8 + warp;
    if (RES) {
        int t = threadIdx.x;
        if (t < 128) {
            float mu = pstat[t] * (1.f / NN);
            float var = pstat[128 + t] * (1.f / NN) - mu * mu;
            float r = rsqrtf(var + 1e-5f);
            psc[t] = pgamma[t] * r;
            psh[t] = pbeta[t] - mu * pgamma[t] * r;
        }
        __syncthreads();
    }
    int start = rowptr[node], end = rowptr[node + 1];
    int deg = end - start;
    float4 er = er4[node];
    int hl = lane >> 3;
    int c0 = lane * 4;

    float4 acc = make_float4(0.f, 0.f, 0.f, 0.f);
    if (RES) {
        float4 h = *(const float4*)&hin[(size_t)node * 128 + c0];
        acc.x = eluf(h.x * psc[c0] + psh[c0]);
        acc.y = eluf(h.y * psc[c0 + 1] + psh[c0 + 1]);
        acc.z = eluf(h.z * psc[c0 + 2] + psh[c0 + 2]);
        acc.w = eluf(h.w * psc[c0 + 3] + psh[c0 + 3]);
    }

    if (deg <= 32) {
        bool on = lane < deg;
        int s = on ? csr[start + lane] : 0;
        float4 v = make_float4(-3e38f, -3e38f, -3e38f, -3e38f);
        if (on) {
            float4 e = el4[s];
            v.x = lrelu(e.x + er.x); v.y = lrelu(e.y + er.y);
            v.z = lrelu(e.z + er.z); v.w = lrelu(e.w + er.w);
        }
        float4 mx = v;
#pragma unroll
        for (int o = 16; o > 0; o >>= 1) {
            mx.x = fmaxf(mx.x, __shfl_xor_sync(0xffffffffu, mx.x, o));
            mx.y = fmaxf(mx.y, __shfl_xor_sync(0xffffffffu, mx.y, o));
            mx.z = fmaxf(mx.z, __shfl_xor_sync(0xffffffffu, mx.z, o));
            mx.w = fmaxf(mx.w, __shfl_xor_sync(0xffffffffu, mx.w, o));
        }
        float4 ex = make_float4(0.f, 0.f, 0.f, 0.f);
        if (on) {
            ex.x = __expf(v.x - mx.x); ex.y = __expf(v.y - mx.y);
            ex.z = __expf(v.z - mx.z); ex.w = __expf(v.w - mx.w);
        }
        float4 sm4 = ex;
#pragma unroll
        for (int o = 16; o > 0; o >>= 1) {
            sm4.x += __shfl_xor_sync(0xffffffffu, sm4.x, o);
            sm4.y += __shfl_xor_sync(0xffffffffu, sm4.y, o);
            sm4.z += __shfl_xor_sync(0xffffffffu, sm4.z, o);
            sm4.w += __shfl_xor_sync(0xffffffffu, sm4.w, o);
        }
        s_sj[warp][lane] = s;
        float4 aex = make_float4(ex.x / sm4.x, ex.y / sm4.y, ex.z / sm4.z, ex.w / sm4.w);
        *(float4*)&s_a[warp][lane][0] = aex;
        __syncwarp();
        // 4-wide software-pipelined gather
        int j = 0;
        for (; j + 4 <= deg; j += 4) {
            int sj0 = s_sj[warp][j],     sj1 = s_sj[warp][j + 1];
            int sj2 = s_sj[warp][j + 2], sj3 = s_sj[warp][j + 3];
            float a0 = s_a[warp][j][hl],     a1 = s_a[warp][j + 1][hl];
            float a2 = s_a[warp][j + 2][hl], a3 = s_a[warp][j + 3][hl];
            uint2 r0 = *(const uint2*)(feat + (size_t)sj0 * 128 + c0);
            uint2 r1 = *(const uint2*)(feat + (size_t)sj1 * 128 + c0);
            uint2 r2 = *(const uint2*)(feat + (size_t)sj2 * 128 + c0);
            uint2 r3 = *(const uint2*)(feat + (size_t)sj3 * 128 + c0);
            float2 p0 = __half22float2(*(__half2*)&r0.x), q0 = __half22float2(*(__half2*)&r0.y);
            float2 p1 = __half22float2(*(__half2*)&r1.x), q1 = __half22float2(*(__half2*)&r1.y);
            float2 p2 = __half22float2(*(__half2*)&r2.x), q2 = __half22float2(*(__half2*)&r2.y);
            float2 p3 = __half22float2(*(__half2*)&r3.x), q3 = __half22float2(*(__half2*)&r3.y);
            acc.x += p0.x * a0 + p1.x * a1 + p2.x * a2 + p3.x * a3;
            acc.y += p0.y * a0 + p1.y * a1 + p2.y * a2 + p3.y * a3;
            acc.z += q0.x * a0 + q1.x * a1 + q2.x * a2 + q3.x * a3;
            acc.w += q0.y * a0 + q1.y * a1 + q2.y * a2 + q3.y * a3;
        }
        for (; j < deg; j++) {
            int sj = s_sj[warp][j];
            float a = s_a[warp][j][hl];
            uint2 raw = *(const uint2*)(feat + (size_t)sj * 128 + c0);
            float2 f01 = __half22float2(*(__half2*)&raw.x);
            float2 f23 = __half22float2(*(__half2*)&raw.y);
            acc.x += f01.x * a; acc.y += f01.y * a;
            acc.z += f23.x * a; acc.w += f23.y * a;
        }
    } else {
        float mx0 = -3e38f, mx1 = -3e38f, mx2 = -3e38f, mx3 = -3e38f;
        for (int k = start + lane; k < end; k += 32) {
            int s = csr[k];
            float4 e = el4[s];
            mx0 = fmaxf(mx0, lrelu(e.x + er.x)); mx1 = fmaxf(mx1, lrelu(e.y + er.y));
            mx2 = fmaxf(mx2, lrelu(e.z + er.z)); mx3 = fmaxf(mx3, lrelu(e.w + er.w));
        }
#pragma unroll
        for (int o = 16; o > 0; o >>= 1) {
            mx0 = fmaxf(mx0, __shfl_xor_sync(0xffffffffu, mx0, o));
            mx1 = fmaxf(mx1, __shfl_xor_sync(0xffffffffu, mx1, o));
            mx2 = fmaxf(mx2, __shfl_xor_sync(0xffffffffu, mx2, o));
            mx3 = fmaxf(mx3, __shfl_xor_sync(0xffffffffu, mx3, o));
        }
        float s0 = 0.f, s1 = 0.f, s2 = 0.f, s3 = 0.f;
        for (int k = start + lane; k < end; k += 32) {
            int s = csr[k];
            float4 e = el4[s];
            s0 += __expf(lrelu(e.x + er.x) - mx0);
            s1 += __expf(lrelu(e.y + er.y) - mx1);
            s2 += __expf(lrelu(e.z + er.z) - mx2);
            s3 += __expf(lrelu(e.w + er.w) - mx3);
        }
#pragma unroll
        for (int o = 16; o > 0; o >>= 1) {
            s0 += __shfl_xor_sync(0xffffffffu, s0, o);
            s1 += __shfl_xor_sync(0xffffffffu, s1, o);
            s2 += __shfl_xor_sync(0xffffffffu, s2, o);
            s3 += __shfl_xor_sync(0xffffffffu, s3, o);
        }
        float mxh = hl == 0 ? mx0 : hl == 1 ? mx1 : hl == 2 ? mx2 : mx3;
        float invh = 1.f / (hl == 0 ? s0 : hl == 1 ? s1 : hl == 2 ? s2 : s3);
        float erh = hl == 0 ? er.x : hl == 1 ? er.y : hl == 2 ? er.z : er.w;
#pragma unroll 2
        for (int k = start; k < end; k++) {
            int s = csr[k];
            float4 e = el4[s];
            float ev = hl == 0 ? e.x : hl == 1 ? e.y : hl == 2 ? e.z : e.w;
            float a = __expf(lrelu(ev + erh) - mxh) * invh;
            uint2 raw = *(const uint2*)(feat + (size_t)s * 128 + c0);
            float2 f01 = __half22float2(*(__half2*)&raw.x);
            float2 f23 = __half22float2(*(__half2*)&raw.y);
            acc.x += f01.x * a; acc.y += f01.y * a;
            acc.z += f23.x * a; acc.w += f23.y * a;
        }
    }
    if (ACT) {
        acc.x = eluf(acc.x); acc.y = eluf(acc.y);
        acc.z = eluf(acc.z); acc.w = eluf(acc.w);
    }
    float sn = snorm[node];
    acc.x *= sn; acc.y *= sn; acc.z *= sn; acc.w *= sn;
    *(float4*)&out[(size_t)node * 128 + c0] = acc;

    ((float4*)bs)[warp * 32 + lane] = acc;
    ((float4*)bq)[warp * 32 + lane] =
        make_float4(acc.x * acc.x, acc.y * acc.y, acc.z * acc.z, acc.w * acc.w);
    __syncthreads();
    int t = threadIdx.x;
    if (t < 128) {
        float s = 0.f, q = 0.f;
#pragma unroll
        for (int w = 0; w < 8; w++) { s += bs[w * 128 + t]; q += bq[w * 128 + t]; }
        atomicAdd(&bnstat[t], s);
        atomicAdd(&bnstat[128 + t], q);
    }
}

// ---------------- classifier: HMMA 128->64 (A split, W fp16), then 64->2 -----
__global__ void k_cls(const float* __restrict__ H, const float* __restrict__ w1,
                      const float* __restrict__ b1, const float* __restrict__ w2,
                      const float* __restrict__ b2, const float* __restrict__ stat,
                      const float* __restrict__ gamma, const float* __restrict__ beta,
                      float* __restrict__ out) {
    extern __shared__ __half smh[];
    __half* sW   = smh;                  // 128 x 72
    __half* sAhi = sW + 128 * 72;        // 64 x 136
    __half* sAlo = sAhi + 64 * 136;      // 64 x 136
    __shared__ float sc[128], shf[128];
    int tid = threadIdx.x, warp = tid >> 5;
    int row0 = blockIdx.x * 64;
    if (tid < 128) {
        float mu = stat[tid] * (1.f / NN);
        float var = stat[128 + tid] * (1.f / NN) - mu * mu;
        float r = rsqrtf(var + 1e-5f);
        sc[tid] = gamma[tid] * r;
        shf[tid] = beta[tid] - mu * gamma[tid] * r;
    }
    __syncthreads();

    for (int p = tid; p < 2048; p += 256) {
        int r = p >> 4, c = (p & 15) * 4;
        float4 v = *(const float4*)&w1[(size_t)r * 64 + c];
        sW[r * 72 + c]     = __float2half_rn(v.x);
        sW[r * 72 + c + 1] = __float2half_rn(v.y);
        sW[r * 72 + c + 2] = __float2half_rn(v.z);
        sW[r * 72 + c + 3] = __float2half_rn(v.w);
    }
    for (int p = tid; p < 2048; p += 256) {
        int row = p >> 5, c = (p & 31) * 4;
        int gr = row0 + row;
        float4 v = make_float4(0.f, 0.f, 0.f, 0.f);
        if (gr < NN) {
            v = *(const float4*)&H[(size_t)gr * 128 + c];
            v.x = eluf(v.x * sc[c] + shf[c]);
            v.y = eluf(v.y * sc[c + 1] + shf[c + 1]);
            v.z = eluf(v.z * sc[c + 2] + shf[c + 2]);
            v.w = eluf(v.w * sc[c + 3] + shf[c + 3]);
        }
        split2h(v.x, sAhi[row * 136 + c], sAlo[row * 136 + c]);
        split2h(v.y, sAhi[row * 136 + c + 1], sAlo[row * 136 + c + 1]);
        split2h(v.z, sAhi[row * 136 + c + 2], sAlo[row * 136 + c + 2]);
        split2h(v.w, sAhi[row * 136 + c + 3], sAlo[row * 136 + c + 3]);
    }
    __syncthreads();

    int mrow = (warp & 3) * 16;
    int ncol = (warp >> 2) * 32;
    wmma::fragment<wmma::accumulator, 16, 16, 16, float> fc[2];
#pragma unroll
    for (int i = 0; i < 2; i++) wmma::fill_fragment(fc[i], 0.f);
#pragma unroll
    for (int ks = 0; ks < 8; ks++) {
        wmma::fragment<wmma::matrix_a, 16, 16, 16, __half, wmma::row_major> fah, fal;
        wmma::load_matrix_sync(fah, sAhi + mrow * 136 + ks * 16, 136);
        wmma::load_matrix_sync(fal, sAlo + mrow * 136 + ks * 16, 136);
#pragma unroll
        for (int ct = 0; ct < 2; ct++) {
            wmma::fragment<wmma::matrix_b, 16, 16, 16, __half, wmma::row_major> fb;
            wmma::load_matrix_sync(fb, sW + (ks * 16) * 72 + ncol + ct * 16, 72);
            wmma::mma_sync(fc[ct], fah, fb, fc[ct]);
            wmma::mma_sync(fc[ct], fal, fb, fc[ct]);
        }
    }
    __syncthreads();
    float* stage = (float*)sAhi;  // 64 x 72
#pragma unroll
    for (int ct = 0; ct < 2; ct++)
        wmma::store_matrix_sync(stage + mrow * 72 + ncol + ct * 16, fc[ct], 72,
                                wmma::mem_row_major);
    __syncthreads();
    if (tid < 128) {
        int row = tid >> 1, o = tid & 1;
        int gr = row0 + row;
        if (gr < NN) {
            float s = b2[o];
            for (int k = 0; k < 64; k++) {
                float hv = stage[row * 72 + k] + b1[k];
                hv = hv > 0.f ? hv : 0.f;
                s += hv * w2[k * 2 + o];
            }
            out[(size_t)gr * 2 + o] = s;
        }
    }
}

// ---------------- host orchestration -----------------------------------------
extern "C" void kernel_launch(void* const* d_in, const int* in_sizes, int n_in,
                              void* d_out, int out_size) {
    const int* x = (const int*)d_in[0];
    const int* src = (const int*)d_in[1];
    const int* dst = (const int*)d_in[2];
    const float* snorm_n = (const float*)d_in[3];
    const float* embed = (const float*)d_in[5];
    const float* W[3] = {(const float*)d_in[6], (const float*)d_in[11], (const float*)d_in[16]};
    const float* al[3] = {(const float*)d_in[7], (const float*)d_in[12], (const float*)d_in[17]};
    const float* ar[3] = {(const float*)d_in[8], (const float*)d_in[13], (const float*)d_in[18]};
    const float* gamma[3] = {(const float*)d_in[9], (const float*)d_in[14], (const float*)d_in[19]};
    const float* beta[3] = {(const float*)d_in[10], (const float*)d_in[15], (const float*)d_in[20]};
    const float* cls1_w = (const float*)d_in[21];
    const float* cls1_b = (const float*)d_in[22];
    const float* cls2_w = (const float*)d_in[23];
    const float* cls2_b = (const float*)d_in[24];
    float* out = (float*)d_out;

    float *h0, *h1, *el, *er, *bnstat;
    __half* feath;
    int *deg, *rowptr, *cursor, *csr, *partial, *poff;
    cudaGetSymbolAddress((void**)&h0, g_h0);
    cudaGetSymbolAddress((void**)&h1, g_h1);
    cudaGetSymbolAddress((void**)&feath, g_feath);
    cudaGetSymbolAddress((void**)&el, g_el);
    cudaGetSymbolAddress((void**)&er, g_er);
    cudaGetSymbolAddress((void**)&bnstat, g_bnstat);
    cudaGetSymbolAddress((void**)&deg, g_deg);
    cudaGetSymbolAddress((void**)&rowptr, g_rowptr);
    cudaGetSymbolAddress((void**)&cursor, g_cursor);
    cudaGetSymbolAddress((void**)&csr, g_csr);
    cudaGetSymbolAddress((void**)&partial, g_partial);
    cudaGetSymbolAddress((void**)&poff, g_poff);

    const int GEMM_SMEM = (128 * 136 + 2 * 64 * 136) * 2;  // 69632
    const int CLS_SMEM  = (128 * 72 + 2 * 64 * 136) * 2;   // 53248
    static bool attr_done = false;
    if (!attr_done) {
        cudaFuncSetAttribute(k_gemm<true>, cudaFuncAttributeMaxDynamicSharedMemorySize, GEMM_SMEM);
        cudaFuncSetAttribute(k_gemm<false>, cudaFuncAttributeMaxDynamicSharedMemorySize, GEMM_SMEM);
        cudaFuncSetAttribute(k_cls, cudaFuncAttributeMaxDynamicSharedMemorySize, CLS_SMEM);
        attr_done = true;
    }
    const int NSCAN = (NN + 255) / 256;  // 196

    cudaMemsetAsync(deg, 0, NN * sizeof(int), 0);
    cudaMemsetAsync(bnstat, 0, 3 * 256 * sizeof(float), 0);

    k_hist<<<(EE + 255) / 256, 256>>>(dst, deg);
    k_scan1<<<NSCAN, 256>>>(deg, partial);
    k_scan2<<<1, 256>>>(partial, poff, NSCAN);
    k_gemm<true><<<PGRID, 256, GEMM_SMEM>>>(nullptr, x, embed, W[0],
                                            nullptr, nullptr, nullptr,
                                            al[0], ar[0], feath, el, er);
    k_scan3<<<NSCAN, 256>>>(deg, poff, rowptr, cursor);
    k_fill<<<(EE + 255) / 256, 256>>>(src, dst, cursor, csr);
    k_agg<false, false><<<NN / 8, 256>>>(feath, nullptr, (const float4*)el,
                                         (const float4*)er, snorm_n, rowptr, csr,
                                         h0, &bnstat[0], nullptr, nullptr, nullptr);
    // layer 1
    k_gemm<false><<<PGRID, 256, GEMM_SMEM>>>(h0, nullptr, nullptr, W[1],
                                             &bnstat[0], gamma[0], beta[0],
                                             al[1], ar[1], feath, el, er);
    k_agg<true, true><<<NN / 8, 256>>>(feath, h0, (const float4*)el,
                                       (const float4*)er, snorm_n, rowptr, csr,
                                       h1, &bnstat[256], &bnstat[0], gamma[0], beta[0]);
    // layer 2
    k_gemm<false><<<PGRID, 256, GEMM_SMEM>>>(h1, nullptr, nullptr, W[2],
                                             &bnstat[256], gamma[1], beta[1],
                                             al[2], ar[2], feath, el, er);
    k_agg<true, true><<<NN / 8, 256>>>(feath, h1, (const float4*)el,
                                       (const float4*)er, snorm_n, rowptr, csr,
                                       h0, &bnstat[512], &bnstat[256], gamma[1], beta[1]);
    // classifier
    k_cls<<<(NN + 63) / 64, 256, CLS_SMEM>>>(h0, cls1_w, cls1_b, cls2_w, cls2_b,
                                             &bnstat[512], gamma[2], beta[2], out);
}